// round 1
// baseline (speedup 1.0000x reference)
#include <cuda_runtime.h>
#include <math.h>

// Problem constants (fixed by the dataset)
#define BB 2
#define SS 2048
#define DD 1024
#define HH 2816
#define EE 8
#define TT (BB*SS)          // 4096 tokens
#define TOPK 2

// ---------------- scratch (device globals; no allocation allowed) ----------
__device__ float g_logits[TT*EE];
__device__ float g_probs [TT*EE];
__device__ float g_nrm   [BB*EE];
__device__ int   g_count [EE];
__device__ int   g_tok   [EE*TT];
__device__ float g_wt    [EE*TT];
// H buffer: row (e*TT + p) holds sin(x@w1)* (x@w3) for expert e, local row p.
__device__ float g_h[EE*TT*HH];   // 8*4096*2816 floats = 369 MB

// ---------------- packed f32x2 helpers (sm_103a FFMA2) ---------------------
typedef unsigned long long ull;

__device__ __forceinline__ ull pk2(float lo, float hi) {
    ull r; asm("mov.b64 %0, {%1,%2};" : "=l"(r) : "f"(lo), "f"(hi)); return r;
}
__device__ __forceinline__ void unpk2(ull v, float& lo, float& hi) {
    asm("mov.b64 {%0,%1}, %2;" : "=f"(lo), "=f"(hi) : "l"(v));
}
__device__ __forceinline__ ull fma2(ull a, ull b, ull c) {
    ull d; asm("fma.rn.f32x2 %0, %1, %2, %3;" : "=l"(d) : "l"(a), "l"(b), "l"(c));
    return d;
}

// ---------------- tiny kernels ---------------------------------------------
__global__ void init_k() {
    if (threadIdx.x < EE) g_count[threadIdx.x] = 0;
}

// logits[t][e] = x[t] . router_w[:,e] + router_b[e]
__global__ void router_k(const float* __restrict__ x,
                         const float* __restrict__ rw,
                         const float* __restrict__ rb) {
    int t = blockIdx.x;
    const float* xr = x + (size_t)t * DD;
    float acc[EE];
#pragma unroll
    for (int e = 0; e < EE; e++) acc[e] = 0.f;
    for (int d = threadIdx.x; d < DD; d += 128) {
        float xv = xr[d];
        const float4* r = (const float4*)(rw + (size_t)d * EE);
        float4 r0 = r[0], r1 = r[1];
        acc[0] += xv * r0.x; acc[1] += xv * r0.y;
        acc[2] += xv * r0.z; acc[3] += xv * r0.w;
        acc[4] += xv * r1.x; acc[5] += xv * r1.y;
        acc[6] += xv * r1.z; acc[7] += xv * r1.w;
    }
    __shared__ float sm[EE][128];
#pragma unroll
    for (int e = 0; e < EE; e++) sm[e][threadIdx.x] = acc[e];
    __syncthreads();
    for (int s = 64; s > 0; s >>= 1) {
        if (threadIdx.x < s) {
#pragma unroll
            for (int e = 0; e < EE; e++)
                sm[e][threadIdx.x] += sm[e][threadIdx.x + s];
        }
        __syncthreads();
    }
    if (threadIdx.x < EE)
        g_logits[(size_t)t * EE + threadIdx.x] = sm[threadIdx.x][0] + rb[threadIdx.x];
}

// nrm[b][e] = max(sqrt(sum_s logits^2), 1e-12)   (F.normalize over dim=1 = S)
__global__ void norm_k() {
    int b = blockIdx.x >> 3, e = blockIdx.x & 7;
    float s = 0.f;
    for (int i = threadIdx.x; i < SS; i += 256) {
        float v = g_logits[((size_t)(b * SS + i)) * EE + e];
        s += v * v;
    }
    __shared__ float sm[256];
    sm[threadIdx.x] = s; __syncthreads();
    for (int st = 128; st > 0; st >>= 1) {
        if (threadIdx.x < st) sm[threadIdx.x] += sm[threadIdx.x + st];
        __syncthreads();
    }
    if (threadIdx.x == 0) g_nrm[blockIdx.x] = fmaxf(sqrtf(sm[0]), 1e-12f);
}

// per-token: normalize, softmax over E, top-2, build expert lists
__global__ void route_k() {
    int t = blockIdx.x * blockDim.x + threadIdx.x;
    if (t >= TT) return;
    int b = t / SS;
    float l[EE];
    float m = -1e30f;
#pragma unroll
    for (int e = 0; e < EE; e++) {
        l[e] = g_logits[(size_t)t * EE + e] / g_nrm[b * EE + e];
        m = fmaxf(m, l[e]);
    }
    float sum = 0.f;
#pragma unroll
    for (int e = 0; e < EE; e++) { l[e] = expf(l[e] - m); sum += l[e]; }
    float inv = 1.f / sum;
#pragma unroll
    for (int e = 0; e < EE; e++) {
        l[e] *= inv;
        g_probs[(size_t)t * EE + e] = l[e];
    }
    // top-2, ties -> lowest index first (strict > keeps earliest) = jax top_k
    int i0 = 0;
#pragma unroll
    for (int e = 1; e < EE; e++) if (l[e] > l[i0]) i0 = e;
    int i1 = -1;
#pragma unroll
    for (int e = 0; e < EE; e++) {
        if (e == i0) continue;
        if (i1 < 0 || l[e] > l[i1]) i1 = e;
    }
    int s0 = atomicAdd(&g_count[i0], 1);
    g_tok[i0 * TT + s0] = t; g_wt[i0 * TT + s0] = l[i0];
    int s1 = atomicAdd(&g_count[i1], 1);
    g_tok[i1 * TT + s1] = t; g_wt[i1 * TT + s1] = l[i1];
}

// aux = sum_{s,e} (1/E - mean_b probs)^2
__global__ void aux_k(float* __restrict__ out_aux) {
    float acc = 0.f;
    for (int i = threadIdx.x; i < SS * EE; i += 256) {
        int s = i >> 3, e = i & 7;
        float a = 0.5f * (g_probs[(size_t)s * EE + e] +
                          g_probs[(size_t)(SS + s) * EE + e]);
        float d = 0.125f - a;
        acc += d * d;
    }
    __shared__ float sm[256];
    sm[threadIdx.x] = acc; __syncthreads();
    for (int st = 128; st > 0; st >>= 1) {
        if (threadIdx.x < st) sm[threadIdx.x] += sm[threadIdx.x + st];
        __syncthreads();
    }
    if (threadIdx.x == 0) out_aux[0] = sm[0];
}

// ---------------- GEMM 1: H = sin(Xg @ w1[e]) * (Xg @ w3[e]) ---------------
#define BM 64
#define BN 64
#define BK 16

__global__ __launch_bounds__(256)
void gemm1_k(const float* __restrict__ x,
             const float* __restrict__ w1,
             const float* __restrict__ w3) {
    int e = blockIdx.z;
    int cnt = g_count[e];
    int row0 = blockIdx.y * BM;
    if (row0 >= cnt) return;
    int col0 = blockIdx.x * BN;

    __shared__ float As[BM][BK + 4];   // +4 keeps 16B align & kills conflicts
    __shared__ float Bs1[BK][BN];
    __shared__ float Bs3[BK][BN];

    int tid = threadIdx.x;
    int la_row = tid >> 2;          // 0..63
    int la_k   = (tid & 3) * 4;     // 0,4,8,12
    int lb_k   = tid >> 4;          // 0..15
    int lb_n   = (tid & 15) * 4;    // 0..60

    int arow = row0 + la_row;
    int tokid = g_tok[e * TT + min(arow, cnt - 1)];
    const float* aptr  = x  + (size_t)tokid * DD + la_k;
    const float* b1ptr = w1 + ((size_t)e * DD + lb_k) * HH + col0 + lb_n;
    const float* b3ptr = w3 + ((size_t)e * DD + lb_k) * HH + col0 + lb_n;

    int tx = tid & 15, ty = tid >> 4;

    ull acc1[4][2], acc3[4][2];
#pragma unroll
    for (int i = 0; i < 4; i++) {
        acc1[i][0] = 0ull; acc1[i][1] = 0ull;
        acc3[i][0] = 0ull; acc3[i][1] = 0ull;
    }

    float4 af  = *(const float4*)aptr;
    float4 b1f = *(const float4*)b1ptr;
    float4 b3f = *(const float4*)b3ptr;

    for (int kk = 0; kk < DD; kk += BK) {
        __syncthreads();
        *(float4*)&As [la_row][la_k] = af;
        *(float4*)&Bs1[lb_k][lb_n]   = b1f;
        *(float4*)&Bs3[lb_k][lb_n]   = b3f;
        __syncthreads();

        int kn = kk + BK;
        if (kn < DD) {
            af  = *(const float4*)(aptr + kn);
            b1f = *(const float4*)(b1ptr + (size_t)kn * HH);
            b3f = *(const float4*)(b3ptr + (size_t)kn * HH);
        }

#pragma unroll
        for (int k = 0; k < BK; k++) {
            float a0 = As[ty * 4 + 0][k];
            float a1 = As[ty * 4 + 1][k];
            float a2 = As[ty * 4 + 2][k];
            float a3 = As[ty * 4 + 3][k];
            ulonglong2 b1p = *(const ulonglong2*)&Bs1[k][tx * 4];
            ulonglong2 b3p = *(const ulonglong2*)&Bs3[k][tx * 4];
            ull ap;
            ap = pk2(a0, a0);
            acc1[0][0] = fma2(ap, b1p.x, acc1[0][0]);
            acc1[0][1] = fma2(ap, b1p.y, acc1[0][1]);
            acc3[0][0] = fma2(ap, b3p.x, acc3[0][0]);
            acc3[0][1] = fma2(ap, b3p.y, acc3[0][1]);
            ap = pk2(a1, a1);
            acc1[1][0] = fma2(ap, b1p.x, acc1[1][0]);
            acc1[1][1] = fma2(ap, b1p.y, acc1[1][1]);
            acc3[1][0] = fma2(ap, b3p.x, acc3[1][0]);
            acc3[1][1] = fma2(ap, b3p.y, acc3[1][1]);
            ap = pk2(a2, a2);
            acc1[2][0] = fma2(ap, b1p.x, acc1[2][0]);
            acc1[2][1] = fma2(ap, b1p.y, acc1[2][1]);
            acc3[2][0] = fma2(ap, b3p.x, acc3[2][0]);
            acc3[2][1] = fma2(ap, b3p.y, acc3[2][1]);
            ap = pk2(a3, a3);
            acc1[3][0] = fma2(ap, b1p.x, acc1[3][0]);
            acc1[3][1] = fma2(ap, b1p.y, acc1[3][1]);
            acc3[3][0] = fma2(ap, b3p.x, acc3[3][0]);
            acc3[3][1] = fma2(ap, b3p.y, acc3[3][1]);
        }
    }

#pragma unroll
    for (int i = 0; i < 4; i++) {
        int m = row0 + ty * 4 + i;
        if (m < cnt) {
            float s0, s1v, s2, s3, g0, g1, g2, g3;
            unpk2(acc1[i][0], s0, s1v); unpk2(acc1[i][1], s2, s3);
            unpk2(acc3[i][0], g0, g1);  unpk2(acc3[i][1], g2, g3);
            float4 o;
            o.x = sinf(s0)  * g0;
            o.y = sinf(s1v) * g1;
            o.z = sinf(s2)  * g2;
            o.w = sinf(s3)  * g3;
            *(float4*)&g_h[((size_t)(e * TT + m)) * HH + col0 + tx * 4] = o;
        }
    }
}

// ---------------- GEMM 2: out[tok] += wt * (H @ w2[e]) ---------------------
__global__ __launch_bounds__(256)
void gemm2_k(const float* __restrict__ w2, float* __restrict__ out) {
    int e = blockIdx.z;
    int cnt = g_count[e];
    int row0 = blockIdx.y * BM;
    if (row0 >= cnt) return;
    int col0 = blockIdx.x * BN;

    __shared__ float As[BM][BK + 4];
    __shared__ float Bs[BK][BN];

    int tid = threadIdx.x;
    int la_row = tid >> 2;
    int la_k   = (tid & 3) * 4;
    int lb_k   = tid >> 4;
    int lb_n   = (tid & 15) * 4;

    const float* aptr = g_h + ((size_t)(e * TT + row0 + la_row)) * HH + la_k;
    const float* bptr = w2 + ((size_t)e * HH + lb_k) * DD + col0 + lb_n;

    int tx = tid & 15, ty = tid >> 4;

    ull acc[4][2];
#pragma unroll
    for (int i = 0; i < 4; i++) { acc[i][0] = 0ull; acc[i][1] = 0ull; }

    float4 af = *(const float4*)aptr;
    float4 bf = *(const float4*)bptr;

    for (int kk = 0; kk < HH; kk += BK) {
        __syncthreads();
        *(float4*)&As[la_row][la_k] = af;
        *(float4*)&Bs[lb_k][lb_n]   = bf;
        __syncthreads();

        int kn = kk + BK;
        if (kn < HH) {
            af = *(const float4*)(aptr + kn);
            bf = *(const float4*)(bptr + (size_t)kn * DD);
        }

#pragma unroll
        for (int k = 0; k < BK; k++) {
            float a0 = As[ty * 4 + 0][k];
            float a1 = As[ty * 4 + 1][k];
            float a2 = As[ty * 4 + 2][k];
            float a3 = As[ty * 4 + 3][k];
            ulonglong2 bp = *(const ulonglong2*)&Bs[k][tx * 4];
            ull ap;
            ap = pk2(a0, a0);
            acc[0][0] = fma2(ap, bp.x, acc[0][0]);
            acc[0][1] = fma2(ap, bp.y, acc[0][1]);
            ap = pk2(a1, a1);
            acc[1][0] = fma2(ap, bp.x, acc[1][0]);
            acc[1][1] = fma2(ap, bp.y, acc[1][1]);
            ap = pk2(a2, a2);
            acc[2][0] = fma2(ap, bp.x, acc[2][0]);
            acc[2][1] = fma2(ap, bp.y, acc[2][1]);
            ap = pk2(a3, a3);
            acc[3][0] = fma2(ap, bp.x, acc[3][0]);
            acc[3][1] = fma2(ap, bp.y, acc[3][1]);
        }
    }

#pragma unroll
    for (int i = 0; i < 4; i++) {
        int m = row0 + ty * 4 + i;
        if (m < cnt) {
            int tok  = g_tok[e * TT + m];
            float wt = g_wt[e * TT + m];
            float v0, v1, v2, v3;
            unpk2(acc[i][0], v0, v1);
            unpk2(acc[i][1], v2, v3);
            float* op = out + (size_t)tok * DD + col0 + tx * 4;
            atomicAdd(op + 0, wt * v0);
            atomicAdd(op + 1, wt * v1);
            atomicAdd(op + 2, wt * v2);
            atomicAdd(op + 3, wt * v3);
        }
    }
}

// ---------------- launch ----------------------------------------------------
extern "C" void kernel_launch(void* const* d_in, const int* in_sizes, int n_in,
                              void* d_out, int out_size) {
    const float* x  = (const float*)d_in[0];
    const float* w1 = (const float*)d_in[1];
    const float* w2 = (const float*)d_in[2];
    const float* w3 = (const float*)d_in[3];
    const float* rw = (const float*)d_in[4];
    const float* rb = (const float*)d_in[5];
    float* out = (float*)d_out;

    // zero the whole output (moe part accumulates; aux slot overwritten)
    cudaMemsetAsync(d_out, 0, (size_t)out_size * sizeof(float));

    init_k<<<1, 32>>>();
    router_k<<<TT, 128>>>(x, rw, rb);
    norm_k<<<BB * EE, 256>>>();
    route_k<<<TT / 256, 256>>>();
    if (out_size > TT * DD) aux_k<<<1, 256>>>(out + (size_t)TT * DD);

    gemm1_k<<<dim3(HH / BN, TT / BM, EE), 256>>>(x, w1, w3);
    gemm2_k<<<dim3(DD / BN, TT / BM, EE), 256>>>(w2, out);
}

// round 6
// speedup vs baseline: 1.9752x; 1.9752x over previous
#include <cuda_runtime.h>
#include <cuda_bf16.h>
#include <math.h>
#include <cstdint>

#define BB 2
#define SS 2048
#define DD 1024
#define HH 2816
#define EE 8
#define TT (BB*SS)

// ---------------- scratch (device globals; total ~386MB) --------------------
__device__ float g_logits[TT*EE];
__device__ float g_probs [TT*EE];
__device__ float g_nrm   [BB*EE];
__device__ int   g_count [EE];
__device__ int   g_tok   [EE*TT];
__device__ float g_wt    [EE*TT];

__device__ __align__(256) __nv_bfloat16 d_xh[TT*DD], d_xl[TT*DD];     // 16.8MB
// H hi/lo interleaved: row (e*TT+r) -> hi at (row*2)*HH, lo at (row*2+1)*HH
__device__ __align__(256) __nv_bfloat16 d_h2[(size_t)EE*TT*2*HH];     // 369MB

// ---------------- PTX helpers ------------------------------------------------
__device__ __forceinline__ uint32_t smem_u32(const void* p) {
    uint32_t a;
    asm("{ .reg .u64 t; cvta.to.shared.u64 t, %1; cvt.u32.u64 %0, t; }"
        : "=r"(a) : "l"(p));
    return a;
}
#define SW64(o)  ((uint32_t)(o) ^ ((((uint32_t)(o)) >> 3) & 0x30))
#define SW128(o) ((uint32_t)(o) ^ ((((uint32_t)(o)) >> 3) & 0x70))

__device__ __forceinline__ void cp16(uint32_t dst, const void* src) {
    asm volatile("cp.async.cg.shared.global [%0], [%1], 16;"
                 :: "r"(dst), "l"(__cvta_generic_to_global(src)) : "memory");
}
#define CP_COMMIT() asm volatile("cp.async.commit_group;" ::: "memory")
#define CP_WAIT0()  asm volatile("cp.async.wait_group 0;" ::: "memory")

__device__ __forceinline__ void ldsm4(uint32_t& r0, uint32_t& r1,
                                      uint32_t& r2, uint32_t& r3, uint32_t a) {
    asm volatile("ldmatrix.sync.aligned.m8n8.x4.shared.b16 {%0,%1,%2,%3}, [%4];"
                 : "=r"(r0), "=r"(r1), "=r"(r2), "=r"(r3) : "r"(a));
}
__device__ __forceinline__ void ldsm4t(uint32_t& r0, uint32_t& r1,
                                       uint32_t& r2, uint32_t& r3, uint32_t a) {
    asm volatile("ldmatrix.sync.aligned.m8n8.x4.trans.shared.b16 {%0,%1,%2,%3}, [%4];"
                 : "=r"(r0), "=r"(r1), "=r"(r2), "=r"(r3) : "r"(a));
}
__device__ __forceinline__ void mma16816(float* c,
        uint32_t a0, uint32_t a1, uint32_t a2, uint32_t a3,
        uint32_t b0, uint32_t b1) {
    asm volatile("mma.sync.aligned.m16n8k16.row.col.f32.bf16.bf16.f32 "
        "{%0,%1,%2,%3},{%4,%5,%6,%7},{%8,%9},{%0,%1,%2,%3};"
        : "+f"(c[0]), "+f"(c[1]), "+f"(c[2]), "+f"(c[3])
        : "r"(a0), "r"(a1), "r"(a2), "r"(a3), "r"(b0), "r"(b1));
}

// ---------------- tiny kernels (verbatim R1, proven) -------------------------
__global__ void init_k() { if (threadIdx.x < EE) g_count[threadIdx.x] = 0; }

__global__ void router_k(const float* __restrict__ x,
                         const float* __restrict__ rw,
                         const float* __restrict__ rb) {
    int t = blockIdx.x;
    const float* xr = x + (size_t)t * DD;
    float acc[EE];
#pragma unroll
    for (int e = 0; e < EE; e++) acc[e] = 0.f;
    for (int d = threadIdx.x; d < DD; d += 128) {
        float xv = xr[d];
        const float4* r = (const float4*)(rw + (size_t)d * EE);
        float4 r0 = r[0], r1 = r[1];
        acc[0] += xv*r0.x; acc[1] += xv*r0.y; acc[2] += xv*r0.z; acc[3] += xv*r0.w;
        acc[4] += xv*r1.x; acc[5] += xv*r1.y; acc[6] += xv*r1.z; acc[7] += xv*r1.w;
    }
    __shared__ float sm[EE][128];
#pragma unroll
    for (int e = 0; e < EE; e++) sm[e][threadIdx.x] = acc[e];
    __syncthreads();
    for (int s = 64; s > 0; s >>= 1) {
        if (threadIdx.x < s)
#pragma unroll
            for (int e = 0; e < EE; e++) sm[e][threadIdx.x] += sm[e][threadIdx.x + s];
        __syncthreads();
    }
    if (threadIdx.x < EE)
        g_logits[(size_t)t*EE + threadIdx.x] = sm[threadIdx.x][0] + rb[threadIdx.x];
}

__global__ void norm_k() {
    int b = blockIdx.x >> 3, e = blockIdx.x & 7;
    float s = 0.f;
    for (int i = threadIdx.x; i < SS; i += 256) {
        float v = g_logits[((size_t)(b*SS + i))*EE + e];
        s += v*v;
    }
    __shared__ float sm[256];
    sm[threadIdx.x] = s; __syncthreads();
    for (int st = 128; st > 0; st >>= 1) {
        if (threadIdx.x < st) sm[threadIdx.x] += sm[threadIdx.x + st];
        __syncthreads();
    }
    if (threadIdx.x == 0) g_nrm[blockIdx.x] = fmaxf(sqrtf(sm[0]), 1e-12f);
}

__global__ void route_k() {
    int t = blockIdx.x*blockDim.x + threadIdx.x;
    if (t >= TT) return;
    int b = t / SS;
    float l[EE]; float m = -1e30f;
#pragma unroll
    for (int e = 0; e < EE; e++) {
        l[e] = g_logits[(size_t)t*EE + e] / g_nrm[b*EE + e];
        m = fmaxf(m, l[e]);
    }
    float sum = 0.f;
#pragma unroll
    for (int e = 0; e < EE; e++) { l[e] = expf(l[e]-m); sum += l[e]; }
    float inv = 1.f/sum;
#pragma unroll
    for (int e = 0; e < EE; e++) { l[e] *= inv; g_probs[(size_t)t*EE + e] = l[e]; }
    int i0 = 0;
#pragma unroll
    for (int e = 1; e < EE; e++) if (l[e] > l[i0]) i0 = e;
    int i1 = -1;
#pragma unroll
    for (int e = 0; e < EE; e++) {
        if (e == i0) continue;
        if (i1 < 0 || l[e] > l[i1]) i1 = e;
    }
    int s0 = atomicAdd(&g_count[i0], 1);
    g_tok[i0*TT + s0] = t; g_wt[i0*TT + s0] = l[i0];
    int s1 = atomicAdd(&g_count[i1], 1);
    g_tok[i1*TT + s1] = t; g_wt[i1*TT + s1] = l[i1];
}

__global__ void aux_k(float* __restrict__ out_aux) {
    float acc = 0.f;
    for (int i = threadIdx.x; i < SS*EE; i += 256) {
        int s = i >> 3, e = i & 7;
        float a = 0.5f*(g_probs[(size_t)s*EE + e] + g_probs[(size_t)(SS+s)*EE + e]);
        float d = 0.125f - a;
        acc += d*d;
    }
    __shared__ float sm[256];
    sm[threadIdx.x] = acc; __syncthreads();
    for (int st = 128; st > 0; st >>= 1) {
        if (threadIdx.x < st) sm[threadIdx.x] += sm[threadIdx.x + st];
        __syncthreads();
    }
    if (threadIdx.x == 0) out_aux[0] = sm[0];
}

// ---------------- x conversion ----------------------------------------------
__device__ __forceinline__ void split1(float v, __nv_bfloat16& h, __nv_bfloat16& l) {
    h = __float2bfloat16(v);
    l = __float2bfloat16(v - __bfloat162float(h));
}

__global__ void splitx_k(const float* __restrict__ x) {
    int i = blockIdx.x*blockDim.x + threadIdx.x;   // i indexes float4
    float4 v = ((const float4*)x)[i];
    __nv_bfloat16 h0,l0,h1,l1,h2,l2,h3,l3;
    split1(v.x,h0,l0); split1(v.y,h1,l1); split1(v.z,h2,l2); split1(v.w,h3,l3);
    __nv_bfloat162* ph = (__nv_bfloat162*)d_xh;
    __nv_bfloat162* pl = (__nv_bfloat162*)d_xl;
    ph[i*2]   = __nv_bfloat162(h0,h1);  ph[i*2+1] = __nv_bfloat162(h2,h3);
    pl[i*2]   = __nv_bfloat162(l0,l1);  pl[i*2+1] = __nv_bfloat162(l2,l3);
}

// pack 4 bf16 into 8 bytes
union BP4 { unsigned long long u; __nv_bfloat16 h[4]; };

// ---------------- GEMM1 (HMMA): H = __sinf(Xg@w1) * (Xg@w3) ------------------
// M=128, N=64, K-stage=32.  A: K-major 64B rows SW64 (ldmatrix).
// B: MN-major 128B rows SW128 (ldmatrix.trans), converted fp32->bf16 in-kernel.
// smem: XH 0 (8K) | XL 8192 | B1H 16384 (4K) | B1L 20480 | B3H 24576 |
//       B3L 28672 | stok @ 32768  -> total 33280
#define G1_SMEM 33280

__global__ __launch_bounds__(256, 1)
void gemm1_k(const float* __restrict__ w1, const float* __restrict__ w3) {
    extern __shared__ char smem[];
    int e = blockIdx.z;
    int cnt = g_count[e];
    int row0 = blockIdx.y * 128;
    if (row0 >= cnt) return;
    int col0 = blockIdx.x * 64;

    int tid = threadIdx.x, wid = tid >> 5, lane = tid & 31;
    uint32_t sb = smem_u32(smem);
    int* stok = (int*)(smem + 32768);

    if (tid < 128) stok[tid] = g_tok[e*TT + min(row0 + tid, cnt-1)];
    __syncthreads();

    int warpM = (wid & 1) * 64;
    int warpN = (wid >> 1) * 16;
    int fr  = (lane & 7) + ((lane >> 3) & 1) * 8;   // ldmatrix row-in-16
    int fkb = (lane >> 4) * 16;                      // 16B col select

    float c1[4][2][4], c3[4][2][4];
#pragma unroll
    for (int i = 0; i < 4; i++)
#pragma unroll
        for (int j = 0; j < 2; j++)
#pragma unroll
            for (int r = 0; r < 4; r++) { c1[i][j][r] = 0.f; c3[i][j][r] = 0.f; }

    for (int s = 0; s < DD/32; s++) {
        int kk = s * 32;
        __syncthreads();                 // prior stage fully consumed
        // ---- A: cp.async, 1024 chunks (hi 512 + lo 512), 4 per thread ----
#pragma unroll
        for (int i = 0; i < 4; i++) {
            int g = tid + 256*i;
            int buf = g >> 9, idx = g & 511;
            int row = idx >> 2, c = idx & 3;
            const __nv_bfloat16* src =
                (buf ? d_xl : d_xh) + (size_t)stok[row]*DD + kk + c*8;
            cp16(sb + buf*8192 + SW64(row*64 + c*16), src);
        }
        CP_COMMIT();
        // ---- B: LDG fp32 + split + STS, 1024 float4, 4 per thread ----
#pragma unroll
        for (int i = 0; i < 4; i++) {
            int g = tid + 256*i;
            int mat = g >> 9, idx = g & 511;
            int krow = idx >> 4, nch = idx & 15;
            const float* wp = mat ? w3 : w1;
            float4 v = *(const float4*)(wp +
                ((size_t)(e*DD + kk + krow))*HH + col0 + nch*4);
            BP4 ph, pl;
            split1(v.x, ph.h[0], pl.h[0]);
            split1(v.y, ph.h[1], pl.h[1]);
            split1(v.z, ph.h[2], pl.h[2]);
            split1(v.w, ph.h[3], pl.h[3]);
            uint32_t off = SW128(krow*128 + nch*8);
            *(unsigned long long*)(smem + 16384 + mat*8192 + off)        = ph.u;
            *(unsigned long long*)(smem + 16384 + mat*8192 + 4096 + off) = pl.u;
        }
        CP_WAIT0();
        __syncthreads();

        // ---- compute: 2 k16 steps ----
#pragma unroll
        for (int k16 = 0; k16 < 2; k16++) {
            uint32_t ah[4][4], al[4][4];
#pragma unroll
            for (int mt = 0; mt < 4; mt++) {
                uint32_t offA = SW64((warpM + mt*16 + fr)*64 + k16*32 + fkb);
                ldsm4(ah[mt][0], ah[mt][1], ah[mt][2], ah[mt][3], sb + offA);
                ldsm4(al[mt][0], al[mt][1], al[mt][2], al[mt][3], sb + 8192 + offA);
            }
            uint32_t offB = SW128((k16*16 + fr)*128 + warpN*2 + fkb);
            uint32_t b1h[4], b1l[4], b3h[4], b3l[4];
            ldsm4t(b1h[0], b1h[1], b1h[2], b1h[3], sb + 16384 + offB);
            ldsm4t(b1l[0], b1l[1], b1l[2], b1l[3], sb + 20480 + offB);
            ldsm4t(b3h[0], b3h[1], b3h[2], b3h[3], sb + 24576 + offB);
            ldsm4t(b3l[0], b3l[1], b3l[2], b3l[3], sb + 28672 + offB);
#pragma unroll
            for (int mt = 0; mt < 4; mt++)
#pragma unroll
                for (int nt = 0; nt < 2; nt++) {
                    mma16816(c1[mt][nt], ah[mt][0],ah[mt][1],ah[mt][2],ah[mt][3], b1h[nt*2], b1h[nt*2+1]);
                    mma16816(c1[mt][nt], al[mt][0],al[mt][1],al[mt][2],al[mt][3], b1h[nt*2], b1h[nt*2+1]);
                    mma16816(c1[mt][nt], ah[mt][0],ah[mt][1],ah[mt][2],ah[mt][3], b1l[nt*2], b1l[nt*2+1]);
                    mma16816(c3[mt][nt], ah[mt][0],ah[mt][1],ah[mt][2],ah[mt][3], b3h[nt*2], b3h[nt*2+1]);
                    mma16816(c3[mt][nt], al[mt][0],al[mt][1],al[mt][2],al[mt][3], b3h[nt*2], b3h[nt*2+1]);
                    mma16816(c3[mt][nt], ah[mt][0],ah[mt][1],ah[mt][2],ah[mt][3], b3l[nt*2], b3l[nt*2+1]);
                }
        }
    }

    // epilogue: h = sin(s)*g, split hi/lo, store to d_h2
#pragma unroll
    for (int mt = 0; mt < 4; mt++) {
#pragma unroll
        for (int half = 0; half < 2; half++) {
            int rg = row0 + warpM + mt*16 + (lane >> 2) + half*8;
            if (rg < cnt) {
                size_t rowi = (size_t)(e*TT + rg);
                size_t cb = col0 + warpN + (lane & 3)*2;
#pragma unroll
                for (int nt = 0; nt < 2; nt++) {
                    float s0 = c1[mt][nt][half*2],   g0 = c3[mt][nt][half*2];
                    float s1 = c1[mt][nt][half*2+1], g1 = c3[mt][nt][half*2+1];
                    float v0 = __sinf(s0)*g0, v1 = __sinf(s1)*g1;
                    __nv_bfloat16 h0,l0,h1,l1;
                    split1(v0,h0,l0); split1(v1,h1,l1);
                    *(__nv_bfloat162*)(d_h2 + (rowi*2)*HH   + cb + nt*8) = __nv_bfloat162(h0,h1);
                    *(__nv_bfloat162*)(d_h2 + (rowi*2+1)*HH + cb + nt*8) = __nv_bfloat162(l0,l1);
                }
            }
        }
    }
}

// ---------------- GEMM2 (HMMA): out[tok] += wt * (H @ w2) --------------------
// smem: AH 0 (8K) | AL 8192 | B2H 16384 (4K) | B2L 20480 | ctrl @ 24576
#define G2_SMEM 25600

__global__ __launch_bounds__(256, 1)
void gemm2_k(const float* __restrict__ w2, float* __restrict__ out) {
    extern __shared__ char smem[];
    int e = blockIdx.z;
    int cnt = g_count[e];
    int row0 = blockIdx.y * 128;
    if (row0 >= cnt) return;
    int col0 = blockIdx.x * 64;

    int tid = threadIdx.x, wid = tid >> 5, lane = tid & 31;
    uint32_t sb = smem_u32(smem);
    int*   stok = (int*)(smem + 24576);
    float* swt  = (float*)(smem + 24576 + 512);

    if (tid < 128) {
        int r = min(row0 + tid, cnt-1);
        stok[tid] = g_tok[e*TT + r];
        swt[tid]  = g_wt[e*TT + r];
    }
    __syncthreads();

    int warpM = (wid & 1) * 64;
    int warpN = (wid >> 1) * 16;
    int fr  = (lane & 7) + ((lane >> 3) & 1) * 8;
    int fkb = (lane >> 4) * 16;
    size_t arow0 = (size_t)(e*TT + row0);

    float cc[4][2][4];
#pragma unroll
    for (int i = 0; i < 4; i++)
#pragma unroll
        for (int j = 0; j < 2; j++)
#pragma unroll
            for (int r = 0; r < 4; r++) cc[i][j][r] = 0.f;

    for (int s = 0; s < HH/32; s++) {
        int kk = s * 32;
        __syncthreads();
        // ---- A (H hi/lo): cp.async, 4 per thread ----
#pragma unroll
        for (int i = 0; i < 4; i++) {
            int g = tid + 256*i;
            int buf = g >> 9, idx = g & 511;
            int row = idx >> 2, c = idx & 3;
            const __nv_bfloat16* src =
                d_h2 + ((arow0 + row)*2 + buf)*HH + kk + c*8;
            cp16(sb + buf*8192 + SW64(row*64 + c*16), src);
        }
        CP_COMMIT();
        // ---- B (w2): LDG fp32 + split + STS, 512 float4, 2 per thread ----
#pragma unroll
        for (int i = 0; i < 2; i++) {
            int g = tid + 256*i;
            int krow = g >> 4, nch = g & 15;
            float4 v = *(const float4*)(w2 +
                ((size_t)(e*HH + kk + krow))*DD + col0 + nch*4);
            BP4 ph, pl;
            split1(v.x, ph.h[0], pl.h[0]);
            split1(v.y, ph.h[1], pl.h[1]);
            split1(v.z, ph.h[2], pl.h[2]);
            split1(v.w, ph.h[3], pl.h[3]);
            uint32_t off = SW128(krow*128 + nch*8);
            *(unsigned long long*)(smem + 16384 + off) = ph.u;
            *(unsigned long long*)(smem + 20480 + off) = pl.u;
        }
        CP_WAIT0();
        __syncthreads();

#pragma unroll
        for (int k16 = 0; k16 < 2; k16++) {
            uint32_t ah[4][4], al[4][4];
#pragma unroll
            for (int mt = 0; mt < 4; mt++) {
                uint32_t offA = SW64((warpM + mt*16 + fr)*64 + k16*32 + fkb);
                ldsm4(ah[mt][0], ah[mt][1], ah[mt][2], ah[mt][3], sb + offA);
                ldsm4(al[mt][0], al[mt][1], al[mt][2], al[mt][3], sb + 8192 + offA);
            }
            uint32_t offB = SW128((k16*16 + fr)*128 + warpN*2 + fkb);
            uint32_t bh[4], bl[4];
            ldsm4t(bh[0], bh[1], bh[2], bh[3], sb + 16384 + offB);
            ldsm4t(bl[0], bl[1], bl[2], bl[3], sb + 20480 + offB);
#pragma unroll
            for (int mt = 0; mt < 4; mt++)
#pragma unroll
                for (int nt = 0; nt < 2; nt++) {
                    mma16816(cc[mt][nt], ah[mt][0],ah[mt][1],ah[mt][2],ah[mt][3], bh[nt*2], bh[nt*2+1]);
                    mma16816(cc[mt][nt], al[mt][0],al[mt][1],al[mt][2],al[mt][3], bh[nt*2], bh[nt*2+1]);
                    mma16816(cc[mt][nt], ah[mt][0],ah[mt][1],ah[mt][2],ah[mt][3], bl[nt*2], bl[nt*2+1]);
                }
        }
    }

    // epilogue: weighted atomic scatter
#pragma unroll
    for (int mt = 0; mt < 4; mt++) {
#pragma unroll
        for (int half = 0; half < 2; half++) {
            int ml = warpM + mt*16 + (lane >> 2) + half*8;
            if (row0 + ml < cnt) {
                int   tok = stok[ml];
                float wt  = swt[ml];
                float* op = out + (size_t)tok*DD + col0 + warpN + (lane & 3)*2;
#pragma unroll
                for (int nt = 0; nt < 2; nt++) {
                    atomicAdd(op + nt*8 + 0, wt * cc[mt][nt][half*2]);
                    atomicAdd(op + nt*8 + 1, wt * cc[mt][nt][half*2+1]);
                }
            }
        }
    }
}

// ---------------- launch -----------------------------------------------------
extern "C" void kernel_launch(void* const* d_in, const int* in_sizes, int n_in,
                              void* d_out, int out_size) {
    const float* x  = (const float*)d_in[0];
    const float* w1 = (const float*)d_in[1];
    const float* w2 = (const float*)d_in[2];
    const float* w3 = (const float*)d_in[3];
    const float* rw = (const float*)d_in[4];
    const float* rb = (const float*)d_in[5];
    float* out = (float*)d_out;

    cudaMemsetAsync(d_out, 0, (size_t)out_size * sizeof(float));

    init_k<<<1, 32>>>();
    router_k<<<TT, 128>>>(x, rw, rb);
    norm_k<<<BB*EE, 256>>>();
    route_k<<<TT/256, 256>>>();
    if (out_size > TT*DD) aux_k<<<1, 256>>>(out + (size_t)TT*DD);

    splitx_k<<<TT*DD/1024, 256>>>(x);

    gemm1_k<<<dim3(HH/64, TT/128, EE), 256, G1_SMEM>>>(w1, w3);
    gemm2_k<<<dim3(DD/64, TT/128, EE), 256, G2_SMEM>>>(w2, out);
}

// round 7
// speedup vs baseline: 2.2927x; 1.1607x over previous
#include <cuda_runtime.h>
#include <cuda_bf16.h>
#include <math.h>
#include <cstdint>

#define BB 2
#define SS 2048
#define DD 1024
#define HH 2816
#define EE 8
#define TT (BB*SS)

// ---------------- scratch (device globals; total ~386MB — proven safe) ------
__device__ float g_logits[TT*EE];
__device__ float g_probs [TT*EE];
__device__ float g_nrm   [BB*EE];
__device__ int   g_count [EE];
__device__ int   g_tok   [EE*TT];
__device__ float g_wt    [EE*TT];

__device__ __align__(256) __nv_bfloat16 d_xh[TT*DD], d_xl[TT*DD];     // 16.8MB
// H hi/lo interleaved: row (e*TT+r) -> hi at (row*2)*HH, lo at (row*2+1)*HH
__device__ __align__(256) __nv_bfloat16 d_h2[(size_t)EE*TT*2*HH];     // 369MB

// ---------------- PTX helpers ------------------------------------------------
__device__ __forceinline__ uint32_t smem_u32(const void* p) {
    uint32_t a;
    asm("{ .reg .u64 t; cvta.to.shared.u64 t, %1; cvt.u32.u64 %0, t; }"
        : "=r"(a) : "l"(p));
    return a;
}
#define SW64(o)  ((uint32_t)(o) ^ ((((uint32_t)(o)) >> 3) & 0x30))
#define SW128(o) ((uint32_t)(o) ^ ((((uint32_t)(o)) >> 3) & 0x70))

__device__ __forceinline__ void cp16(uint32_t dst, const void* src) {
    asm volatile("cp.async.cg.shared.global [%0], [%1], 16;"
                 :: "r"(dst), "l"(__cvta_generic_to_global(src)) : "memory");
}
#define CP_COMMIT() asm volatile("cp.async.commit_group;" ::: "memory")
#define CP_WAIT0()  asm volatile("cp.async.wait_group 0;" ::: "memory")

__device__ __forceinline__ void ldsm4(uint32_t& r0, uint32_t& r1,
                                      uint32_t& r2, uint32_t& r3, uint32_t a) {
    asm volatile("ldmatrix.sync.aligned.m8n8.x4.shared.b16 {%0,%1,%2,%3}, [%4];"
                 : "=r"(r0), "=r"(r1), "=r"(r2), "=r"(r3) : "r"(a));
}
__device__ __forceinline__ void ldsm4t(uint32_t& r0, uint32_t& r1,
                                       uint32_t& r2, uint32_t& r3, uint32_t a) {
    asm volatile("ldmatrix.sync.aligned.m8n8.x4.trans.shared.b16 {%0,%1,%2,%3}, [%4];"
                 : "=r"(r0), "=r"(r1), "=r"(r2), "=r"(r3) : "r"(a));
}
__device__ __forceinline__ void mma16816(float* c,
        uint32_t a0, uint32_t a1, uint32_t a2, uint32_t a3,
        uint32_t b0, uint32_t b1) {
    asm volatile("mma.sync.aligned.m16n8k16.row.col.f32.bf16.bf16.f32 "
        "{%0,%1,%2,%3},{%4,%5,%6,%7},{%8,%9},{%0,%1,%2,%3};"
        : "+f"(c[0]), "+f"(c[1]), "+f"(c[2]), "+f"(c[3])
        : "r"(a0), "r"(a1), "r"(a2), "r"(a3), "r"(b0), "r"(b1));
}

// ---------------- tiny kernels (verbatim R1, proven) -------------------------
__global__ void init_k() { if (threadIdx.x < EE) g_count[threadIdx.x] = 0; }

__global__ void router_k(const float* __restrict__ x,
                         const float* __restrict__ rw,
                         const float* __restrict__ rb) {
    int t = blockIdx.x;
    const float* xr = x + (size_t)t * DD;
    float acc[EE];
#pragma unroll
    for (int e = 0; e < EE; e++) acc[e] = 0.f;
    for (int d = threadIdx.x; d < DD; d += 128) {
        float xv = xr[d];
        const float4* r = (const float4*)(rw + (size_t)d * EE);
        float4 r0 = r[0], r1 = r[1];
        acc[0] += xv*r0.x; acc[1] += xv*r0.y; acc[2] += xv*r0.z; acc[3] += xv*r0.w;
        acc[4] += xv*r1.x; acc[5] += xv*r1.y; acc[6] += xv*r1.z; acc[7] += xv*r1.w;
    }
    __shared__ float sm[EE][128];
#pragma unroll
    for (int e = 0; e < EE; e++) sm[e][threadIdx.x] = acc[e];
    __syncthreads();
    for (int s = 64; s > 0; s >>= 1) {
        if (threadIdx.x < s)
#pragma unroll
            for (int e = 0; e < EE; e++) sm[e][threadIdx.x] += sm[e][threadIdx.x + s];
        __syncthreads();
    }
    if (threadIdx.x < EE)
        g_logits[(size_t)t*EE + threadIdx.x] = sm[threadIdx.x][0] + rb[threadIdx.x];
}

__global__ void norm_k() {
    int b = blockIdx.x >> 3, e = blockIdx.x & 7;
    float s = 0.f;
    for (int i = threadIdx.x; i < SS; i += 256) {
        float v = g_logits[((size_t)(b*SS + i))*EE + e];
        s += v*v;
    }
    __shared__ float sm[256];
    sm[threadIdx.x] = s; __syncthreads();
    for (int st = 128; st > 0; st >>= 1) {
        if (threadIdx.x < st) sm[threadIdx.x] += sm[threadIdx.x + st];
        __syncthreads();
    }
    if (threadIdx.x == 0) g_nrm[blockIdx.x] = fmaxf(sqrtf(sm[0]), 1e-12f);
}

__global__ void route_k() {
    int t = blockIdx.x*blockDim.x + threadIdx.x;
    if (t >= TT) return;
    int b = t / SS;
    float l[EE]; float m = -1e30f;
#pragma unroll
    for (int e = 0; e < EE; e++) {
        l[e] = g_logits[(size_t)t*EE + e] / g_nrm[b*EE + e];
        m = fmaxf(m, l[e]);
    }
    float sum = 0.f;
#pragma unroll
    for (int e = 0; e < EE; e++) { l[e] = expf(l[e]-m); sum += l[e]; }
    float inv = 1.f/sum;
#pragma unroll
    for (int e = 0; e < EE; e++) { l[e] *= inv; g_probs[(size_t)t*EE + e] = l[e]; }
    int i0 = 0;
#pragma unroll
    for (int e = 1; e < EE; e++) if (l[e] > l[i0]) i0 = e;
    int i1 = -1;
#pragma unroll
    for (int e = 0; e < EE; e++) {
        if (e == i0) continue;
        if (i1 < 0 || l[e] > l[i1]) i1 = e;
    }
    int s0 = atomicAdd(&g_count[i0], 1);
    g_tok[i0*TT + s0] = t; g_wt[i0*TT + s0] = l[i0];
    int s1 = atomicAdd(&g_count[i1], 1);
    g_tok[i1*TT + s1] = t; g_wt[i1*TT + s1] = l[i1];
}

__global__ void aux_k(float* __restrict__ out_aux) {
    float acc = 0.f;
    for (int i = threadIdx.x; i < SS*EE; i += 256) {
        int s = i >> 3, e = i & 7;
        float a = 0.5f*(g_probs[(size_t)s*EE + e] + g_probs[(size_t)(SS+s)*EE + e]);
        float d = 0.125f - a;
        acc += d*d;
    }
    __shared__ float sm[256];
    sm[threadIdx.x] = acc; __syncthreads();
    for (int st = 128; st > 0; st >>= 1) {
        if (threadIdx.x < st) sm[threadIdx.x] += sm[threadIdx.x + st];
        __syncthreads();
    }
    if (threadIdx.x == 0) out_aux[0] = sm[0];
}

// ---------------- x conversion ----------------------------------------------
__device__ __forceinline__ void split1(float v, __nv_bfloat16& h, __nv_bfloat16& l) {
    h = __float2bfloat16(v);
    l = __float2bfloat16(v - __bfloat162float(h));
}

__global__ void splitx_k(const float* __restrict__ x) {
    int i = blockIdx.x*blockDim.x + threadIdx.x;   // i indexes float4
    float4 v = ((const float4*)x)[i];
    __nv_bfloat16 h0,l0,h1,l1,h2,l2,h3,l3;
    split1(v.x,h0,l0); split1(v.y,h1,l1); split1(v.z,h2,l2); split1(v.w,h3,l3);
    __nv_bfloat162* ph = (__nv_bfloat162*)d_xh;
    __nv_bfloat162* pl = (__nv_bfloat162*)d_xl;
    ph[i*2]   = __nv_bfloat162(h0,h1);  ph[i*2+1] = __nv_bfloat162(h2,h3);
    pl[i*2]   = __nv_bfloat162(l0,l1);  pl[i*2+1] = __nv_bfloat162(l2,l3);
}

union BP4 { unsigned long long u; __nv_bfloat16 h[4]; };

// ---------------- GEMM1 (HMMA, double-buffered) ------------------------------
// M=128, N=64 per weight matrix; K-stage=32.
// Stage buffer (32KB): XH 0 | XL 8192 | B1H 16384 | B1L 20480 | B3H 24576 | B3L 28672
// Two parity buffers at 0 / 32768; stok @ 65536.
#define G1_STG  32768
#define G1_SMEM (2*G1_STG + 512)
#define G1_NS   (DD/32)

__global__ __launch_bounds__(256, 1)
void gemm1_k(const float* __restrict__ w1, const float* __restrict__ w3) {
    extern __shared__ char smem[];
    int e = blockIdx.z;
    int cnt = g_count[e];
    int row0 = blockIdx.y * 128;
    if (row0 >= cnt) return;
    int col0 = blockIdx.x * 64;

    int tid = threadIdx.x, wid = tid >> 5, lane = tid & 31;
    uint32_t sb = smem_u32(smem);
    int* stok = (int*)(smem + 2*G1_STG);

    if (tid < 128) stok[tid] = g_tok[e*TT + min(row0 + tid, cnt-1)];
    __syncthreads();

    int warpM = (wid & 1) * 64;
    int warpN = (wid >> 1) * 16;
    int fr  = (lane & 7) + ((lane >> 3) & 1) * 8;
    int fkb = (lane >> 4) * 16;

    // per-thread load coords (A: 4 chunks; B: 4 float4)
    int aBuf[4], aRow[4], aCol[4];
    int bMat[4], bKr[4], bNc[4];
#pragma unroll
    for (int i = 0; i < 4; i++) {
        int g = tid + 256*i;
        aBuf[i] = g >> 9; aRow[i] = (g >> 2) & 127; aCol[i] = g & 3;
        bMat[i] = g >> 9; bKr[i]  = (g >> 4) & 31;  bNc[i]  = g & 15;
    }

    auto copyA = [&](int s) {
        uint32_t base = sb + (s & 1)*G1_STG;
        int kk = s*32;
#pragma unroll
        for (int i = 0; i < 4; i++) {
            const __nv_bfloat16* src =
                (aBuf[i] ? d_xl : d_xh) + (size_t)stok[aRow[i]]*DD + kk + aCol[i]*8;
            cp16(base + aBuf[i]*8192 + SW64(aRow[i]*64 + aCol[i]*16), src);
        }
        CP_COMMIT();
    };
    auto ldgB = [&](int s, float4* v) {
        int kk = s*32;
#pragma unroll
        for (int i = 0; i < 4; i++) {
            const float* wp = bMat[i] ? w3 : w1;
            v[i] = *(const float4*)(wp +
                ((size_t)(e*DD + kk + bKr[i]))*HH + col0 + bNc[i]*4);
        }
    };
    auto stsB = [&](int s, const float4* v) {
        char* base = smem + (s & 1)*G1_STG + 16384;
#pragma unroll
        for (int i = 0; i < 4; i++) {
            BP4 ph, pl;
            split1(v[i].x, ph.h[0], pl.h[0]);
            split1(v[i].y, ph.h[1], pl.h[1]);
            split1(v[i].z, ph.h[2], pl.h[2]);
            split1(v[i].w, ph.h[3], pl.h[3]);
            uint32_t off = SW128(bKr[i]*128 + bNc[i]*8);
            *(unsigned long long*)(base + bMat[i]*8192 + off)        = ph.u;
            *(unsigned long long*)(base + bMat[i]*8192 + 4096 + off) = pl.u;
        }
    };

    float c1[4][2][4], c3[4][2][4];
#pragma unroll
    for (int i = 0; i < 4; i++)
#pragma unroll
        for (int j = 0; j < 2; j++)
#pragma unroll
            for (int r = 0; r < 4; r++) { c1[i][j][r] = 0.f; c3[i][j][r] = 0.f; }

    // prologue
    {
        float4 b0[4];
        copyA(0);
        ldgB(0, b0);
        stsB(0, b0);
        CP_WAIT0();
        __syncthreads();
    }

    for (int s = 0; s < G1_NS; s++) {
        float4 bn[4];
        bool more = (s + 1 < G1_NS);
        if (more) { copyA(s + 1); ldgB(s + 1, bn); }

        uint32_t st = sb + (s & 1)*G1_STG;
#pragma unroll
        for (int k16 = 0; k16 < 2; k16++) {
            uint32_t ah[4][4], al[4][4];
#pragma unroll
            for (int mt = 0; mt < 4; mt++) {
                uint32_t offA = SW64((warpM + mt*16 + fr)*64 + k16*32 + fkb);
                ldsm4(ah[mt][0], ah[mt][1], ah[mt][2], ah[mt][3], st + offA);
                ldsm4(al[mt][0], al[mt][1], al[mt][2], al[mt][3], st + 8192 + offA);
            }
            uint32_t offB = SW128((k16*16 + fr)*128 + warpN*2 + fkb);
            uint32_t b1h[4], b1l[4], b3h[4], b3l[4];
            ldsm4t(b1h[0], b1h[1], b1h[2], b1h[3], st + 16384 + offB);
            ldsm4t(b1l[0], b1l[1], b1l[2], b1l[3], st + 20480 + offB);
            ldsm4t(b3h[0], b3h[1], b3h[2], b3h[3], st + 24576 + offB);
            ldsm4t(b3l[0], b3l[1], b3l[2], b3l[3], st + 28672 + offB);
#pragma unroll
            for (int mt = 0; mt < 4; mt++)
#pragma unroll
                for (int nt = 0; nt < 2; nt++) {
                    mma16816(c1[mt][nt], ah[mt][0],ah[mt][1],ah[mt][2],ah[mt][3], b1h[nt*2], b1h[nt*2+1]);
                    mma16816(c1[mt][nt], al[mt][0],al[mt][1],al[mt][2],al[mt][3], b1h[nt*2], b1h[nt*2+1]);
                    mma16816(c1[mt][nt], ah[mt][0],ah[mt][1],ah[mt][2],ah[mt][3], b1l[nt*2], b1l[nt*2+1]);
                    mma16816(c3[mt][nt], ah[mt][0],ah[mt][1],ah[mt][2],ah[mt][3], b3h[nt*2], b3h[nt*2+1]);
                    mma16816(c3[mt][nt], al[mt][0],al[mt][1],al[mt][2],al[mt][3], b3h[nt*2], b3h[nt*2+1]);
                    mma16816(c3[mt][nt], ah[mt][0],ah[mt][1],ah[mt][2],ah[mt][3], b3l[nt*2], b3l[nt*2+1]);
                }
        }
        if (more) {
            stsB(s + 1, bn);
            CP_WAIT0();
            __syncthreads();
        }
    }

    // epilogue
#pragma unroll
    for (int mt = 0; mt < 4; mt++) {
#pragma unroll
        for (int half = 0; half < 2; half++) {
            int rg = row0 + warpM + mt*16 + (lane >> 2) + half*8;
            if (rg < cnt) {
                size_t rowi = (size_t)(e*TT + rg);
                size_t cb = col0 + warpN + (lane & 3)*2;
#pragma unroll
                for (int nt = 0; nt < 2; nt++) {
                    float s0 = c1[mt][nt][half*2],   g0 = c3[mt][nt][half*2];
                    float s1 = c1[mt][nt][half*2+1], g1 = c3[mt][nt][half*2+1];
                    float v0 = __sinf(s0)*g0, v1 = __sinf(s1)*g1;
                    __nv_bfloat16 h0,l0,h1,l1;
                    split1(v0,h0,l0); split1(v1,h1,l1);
                    *(__nv_bfloat162*)(d_h2 + (rowi*2)*HH   + cb + nt*8) = __nv_bfloat162(h0,h1);
                    *(__nv_bfloat162*)(d_h2 + (rowi*2+1)*HH + cb + nt*8) = __nv_bfloat162(l0,l1);
                }
            }
        }
    }
}

// ---------------- GEMM2 (HMMA, double-buffered) ------------------------------
// Stage buffer (24KB): AH 0 | AL 8192 | B2H 16384 | B2L 20480
// Two parity buffers at 0 / 24576; ctrl @ 49152.
#define G2_STG  24576
#define G2_SMEM (2*G2_STG + 1024)
#define G2_NS   (HH/32)

__global__ __launch_bounds__(256, 1)
void gemm2_k(const float* __restrict__ w2, float* __restrict__ out) {
    extern __shared__ char smem[];
    int e = blockIdx.z;
    int cnt = g_count[e];
    int row0 = blockIdx.y * 128;
    if (row0 >= cnt) return;
    int col0 = blockIdx.x * 64;

    int tid = threadIdx.x, wid = tid >> 5, lane = tid & 31;
    uint32_t sb = smem_u32(smem);
    int*   stok = (int*)(smem + 2*G2_STG);
    float* swt  = (float*)(smem + 2*G2_STG + 512);

    if (tid < 128) {
        int r = min(row0 + tid, cnt-1);
        stok[tid] = g_tok[e*TT + r];
        swt[tid]  = g_wt[e*TT + r];
    }
    __syncthreads();

    int warpM = (wid & 1) * 64;
    int warpN = (wid >> 1) * 16;
    int fr  = (lane & 7) + ((lane >> 3) & 1) * 8;
    int fkb = (lane >> 4) * 16;
    size_t arow0 = (size_t)(e*TT + row0);

    int aBuf[4], aRow[4], aCol[4];
    int bKr[2], bNc[2];
#pragma unroll
    for (int i = 0; i < 4; i++) {
        int g = tid + 256*i;
        aBuf[i] = g >> 9; aRow[i] = (g >> 2) & 127; aCol[i] = g & 3;
    }
#pragma unroll
    for (int i = 0; i < 2; i++) {
        int g = tid + 256*i;
        bKr[i] = g >> 4; bNc[i] = g & 15;
    }

    auto copyA = [&](int s) {
        uint32_t base = sb + (s & 1)*G2_STG;
        int kk = s*32;
#pragma unroll
        for (int i = 0; i < 4; i++) {
            const __nv_bfloat16* src =
                d_h2 + ((arow0 + aRow[i])*2 + aBuf[i])*HH + kk + aCol[i]*8;
            cp16(base + aBuf[i]*8192 + SW64(aRow[i]*64 + aCol[i]*16), src);
        }
        CP_COMMIT();
    };
    auto ldgB = [&](int s, float4* v) {
        int kk = s*32;
#pragma unroll
        for (int i = 0; i < 2; i++)
            v[i] = *(const float4*)(w2 +
                ((size_t)(e*HH + kk + bKr[i]))*DD + col0 + bNc[i]*4);
    };
    auto stsB = [&](int s, const float4* v) {
        char* base = smem + (s & 1)*G2_STG + 16384;
#pragma unroll
        for (int i = 0; i < 2; i++) {
            BP4 ph, pl;
            split1(v[i].x, ph.h[0], pl.h[0]);
            split1(v[i].y, ph.h[1], pl.h[1]);
            split1(v[i].z, ph.h[2], pl.h[2]);
            split1(v[i].w, ph.h[3], pl.h[3]);
            uint32_t off = SW128(bKr[i]*128 + bNc[i]*8);
            *(unsigned long long*)(base + off)        = ph.u;
            *(unsigned long long*)(base + 4096 + off) = pl.u;
        }
    };

    float cc[4][2][4];
#pragma unroll
    for (int i = 0; i < 4; i++)
#pragma unroll
        for (int j = 0; j < 2; j++)
#pragma unroll
            for (int r = 0; r < 4; r++) cc[i][j][r] = 0.f;

    {
        float4 b0[2];
        copyA(0);
        ldgB(0, b0);
        stsB(0, b0);
        CP_WAIT0();
        __syncthreads();
    }

    for (int s = 0; s < G2_NS; s++) {
        float4 bn[2];
        bool more = (s + 1 < G2_NS);
        if (more) { copyA(s + 1); ldgB(s + 1, bn); }

        uint32_t st = sb + (s & 1)*G2_STG;
#pragma unroll
        for (int k16 = 0; k16 < 2; k16++) {
            uint32_t ah[4][4], al[4][4];
#pragma unroll
            for (int mt = 0; mt < 4; mt++) {
                uint32_t offA = SW64((warpM + mt*16 + fr)*64 + k16*32 + fkb);
                ldsm4(ah[mt][0], ah[mt][1], ah[mt][2], ah[mt][3], st + offA);
                ldsm4(al[mt][0], al[mt][1], al[mt][2], al[mt][3], st + 8192 + offA);
            }
            uint32_t offB = SW128((k16*16 + fr)*128 + warpN*2 + fkb);
            uint32_t bh[4], bl[4];
            ldsm4t(bh[0], bh[1], bh[2], bh[3], st + 16384 + offB);
            ldsm4t(bl[0], bl[1], bl[2], bl[3], st + 20480 + offB);
#pragma unroll
            for (int mt = 0; mt < 4; mt++)
#pragma unroll
                for (int nt = 0; nt < 2; nt++) {
                    mma16816(cc[mt][nt], ah[mt][0],ah[mt][1],ah[mt][2],ah[mt][3], bh[nt*2], bh[nt*2+1]);
                    mma16816(cc[mt][nt], al[mt][0],al[mt][1],al[mt][2],al[mt][3], bh[nt*2], bh[nt*2+1]);
                    mma16816(cc[mt][nt], ah[mt][0],ah[mt][1],ah[mt][2],ah[mt][3], bl[nt*2], bl[nt*2+1]);
                }
        }
        if (more) {
            stsB(s + 1, bn);
            CP_WAIT0();
            __syncthreads();
        }
    }

    // epilogue: weighted atomic scatter
#pragma unroll
    for (int mt = 0; mt < 4; mt++) {
#pragma unroll
        for (int half = 0; half < 2; half++) {
            int ml = warpM + mt*16 + (lane >> 2) + half*8;
            if (row0 + ml < cnt) {
                int   tok = stok[ml];
                float wt  = swt[ml];
                float* op = out + (size_t)tok*DD + col0 + warpN + (lane & 3)*2;
#pragma unroll
                for (int nt = 0; nt < 2; nt++) {
                    atomicAdd(op + nt*8 + 0, wt * cc[mt][nt][half*2]);
                    atomicAdd(op + nt*8 + 1, wt * cc[mt][nt][half*2+1]);
                }
            }
        }
    }
}

// ---------------- launch -----------------------------------------------------
extern "C" void kernel_launch(void* const* d_in, const int* in_sizes, int n_in,
                              void* d_out, int out_size) {
    const float* x  = (const float*)d_in[0];
    const float* w1 = (const float*)d_in[1];
    const float* w2 = (const float*)d_in[2];
    const float* w3 = (const float*)d_in[3];
    const float* rw = (const float*)d_in[4];
    const float* rb = (const float*)d_in[5];
    float* out = (float*)d_out;

    // host-side config (not stream ops; called every launch, no static guard)
    cudaFuncSetAttribute(gemm1_k, cudaFuncAttributeMaxDynamicSharedMemorySize, G1_SMEM);
    cudaFuncSetAttribute(gemm2_k, cudaFuncAttributeMaxDynamicSharedMemorySize, G2_SMEM);

    cudaMemsetAsync(d_out, 0, (size_t)out_size * sizeof(float));

    init_k<<<1, 32>>>();
    router_k<<<TT, 128>>>(x, rw, rb);
    norm_k<<<BB*EE, 256>>>();
    route_k<<<TT/256, 256>>>();
    if (out_size > TT*DD) aux_k<<<1, 256>>>(out + (size_t)TT*DD);

    splitx_k<<<TT*DD/1024, 256>>>(x);

    gemm1_k<<<dim3(HH/64, TT/128, EE), 256, G1_SMEM>>>(w1, w3);
    gemm2_k<<<dim3(DD/64, TT/128, EE), 256, G2_SMEM>>>(w2, out);
}

// round 8
// speedup vs baseline: 2.4654x; 1.0753x over previous
#include <cuda_runtime.h>
#include <cuda_bf16.h>
#include <math.h>
#include <cstdint>

#define BB 2
#define SS 2048
#define DD 1024
#define HH 2816
#define EE 8
#define TT (BB*SS)

// ---------------- scratch (device globals; total ~386MB — proven safe) ------
__device__ float g_logits[TT*EE];
__device__ float g_probs [TT*EE];
__device__ float g_nrm   [BB*EE];
__device__ int   g_count [EE];
__device__ int   g_tok   [EE*TT];
__device__ float g_wt    [EE*TT];

__device__ __align__(256) __nv_bfloat16 d_xh[TT*DD], d_xl[TT*DD];     // 16.8MB
// H hi/lo interleaved: row (e*TT+r) -> hi at (row*2)*HH, lo at (row*2+1)*HH
__device__ __align__(256) __nv_bfloat16 d_h2[(size_t)EE*TT*2*HH];     // 369MB

// ---------------- PTX helpers ------------------------------------------------
__device__ __forceinline__ uint32_t smem_u32(const void* p) {
    uint32_t a;
    asm("{ .reg .u64 t; cvta.to.shared.u64 t, %1; cvt.u32.u64 %0, t; }"
        : "=r"(a) : "l"(p));
    return a;
}
#define SW64(o)  ((uint32_t)(o) ^ ((((uint32_t)(o)) >> 3) & 0x30))
#define SW128(o) ((uint32_t)(o) ^ ((((uint32_t)(o)) >> 3) & 0x70))

__device__ __forceinline__ void cp16(uint32_t dst, const void* src) {
    asm volatile("cp.async.cg.shared.global [%0], [%1], 16;"
                 :: "r"(dst), "l"(__cvta_generic_to_global(src)) : "memory");
}
#define CP_COMMIT() asm volatile("cp.async.commit_group;" ::: "memory")
#define CP_WAIT0()  asm volatile("cp.async.wait_group 0;" ::: "memory")

__device__ __forceinline__ void ldsm4(uint32_t& r0, uint32_t& r1,
                                      uint32_t& r2, uint32_t& r3, uint32_t a) {
    asm volatile("ldmatrix.sync.aligned.m8n8.x4.shared.b16 {%0,%1,%2,%3}, [%4];"
                 : "=r"(r0), "=r"(r1), "=r"(r2), "=r"(r3) : "r"(a));
}
__device__ __forceinline__ void ldsm4t(uint32_t& r0, uint32_t& r1,
                                       uint32_t& r2, uint32_t& r3, uint32_t a) {
    asm volatile("ldmatrix.sync.aligned.m8n8.x4.trans.shared.b16 {%0,%1,%2,%3}, [%4];"
                 : "=r"(r0), "=r"(r1), "=r"(r2), "=r"(r3) : "r"(a));
}
__device__ __forceinline__ void mma16816(float* c,
        uint32_t a0, uint32_t a1, uint32_t a2, uint32_t a3,
        uint32_t b0, uint32_t b1) {
    asm volatile("mma.sync.aligned.m16n8k16.row.col.f32.bf16.bf16.f32 "
        "{%0,%1,%2,%3},{%4,%5,%6,%7},{%8,%9},{%0,%1,%2,%3};"
        : "+f"(c[0]), "+f"(c[1]), "+f"(c[2]), "+f"(c[3])
        : "r"(a0), "r"(a1), "r"(a2), "r"(a3), "r"(b0), "r"(b1));
}

// ---------------- tiny kernels (verbatim R1, proven) -------------------------
__global__ void init_k() { if (threadIdx.x < EE) g_count[threadIdx.x] = 0; }

__global__ void router_k(const float* __restrict__ x,
                         const float* __restrict__ rw,
                         const float* __restrict__ rb) {
    int t = blockIdx.x;
    const float* xr = x + (size_t)t * DD;
    float acc[EE];
#pragma unroll
    for (int e = 0; e < EE; e++) acc[e] = 0.f;
    for (int d = threadIdx.x; d < DD; d += 128) {
        float xv = xr[d];
        const float4* r = (const float4*)(rw + (size_t)d * EE);
        float4 r0 = r[0], r1 = r[1];
        acc[0] += xv*r0.x; acc[1] += xv*r0.y; acc[2] += xv*r0.z; acc[3] += xv*r0.w;
        acc[4] += xv*r1.x; acc[5] += xv*r1.y; acc[6] += xv*r1.z; acc[7] += xv*r1.w;
    }
    __shared__ float sm[EE][128];
#pragma unroll
    for (int e = 0; e < EE; e++) sm[e][threadIdx.x] = acc[e];
    __syncthreads();
    for (int s = 64; s > 0; s >>= 1) {
        if (threadIdx.x < s)
#pragma unroll
            for (int e = 0; e < EE; e++) sm[e][threadIdx.x] += sm[e][threadIdx.x + s];
        __syncthreads();
    }
    if (threadIdx.x < EE)
        g_logits[(size_t)t*EE + threadIdx.x] = sm[threadIdx.x][0] + rb[threadIdx.x];
}

__global__ void norm_k() {
    int b = blockIdx.x >> 3, e = blockIdx.x & 7;
    float s = 0.f;
    for (int i = threadIdx.x; i < SS; i += 256) {
        float v = g_logits[((size_t)(b*SS + i))*EE + e];
        s += v*v;
    }
    __shared__ float sm[256];
    sm[threadIdx.x] = s; __syncthreads();
    for (int st = 128; st > 0; st >>= 1) {
        if (threadIdx.x < st) sm[threadIdx.x] += sm[threadIdx.x + st];
        __syncthreads();
    }
    if (threadIdx.x == 0) g_nrm[blockIdx.x] = fmaxf(sqrtf(sm[0]), 1e-12f);
}

__global__ void route_k() {
    int t = blockIdx.x*blockDim.x + threadIdx.x;
    if (t >= TT) return;
    int b = t / SS;
    float l[EE]; float m = -1e30f;
#pragma unroll
    for (int e = 0; e < EE; e++) {
        l[e] = g_logits[(size_t)t*EE + e] / g_nrm[b*EE + e];
        m = fmaxf(m, l[e]);
    }
    float sum = 0.f;
#pragma unroll
    for (int e = 0; e < EE; e++) { l[e] = expf(l[e]-m); sum += l[e]; }
    float inv = 1.f/sum;
#pragma unroll
    for (int e = 0; e < EE; e++) { l[e] *= inv; g_probs[(size_t)t*EE + e] = l[e]; }
    int i0 = 0;
#pragma unroll
    for (int e = 1; e < EE; e++) if (l[e] > l[i0]) i0 = e;
    int i1 = -1;
#pragma unroll
    for (int e = 0; e < EE; e++) {
        if (e == i0) continue;
        if (i1 < 0 || l[e] > l[i1]) i1 = e;
    }
    int s0 = atomicAdd(&g_count[i0], 1);
    g_tok[i0*TT + s0] = t; g_wt[i0*TT + s0] = l[i0];
    int s1 = atomicAdd(&g_count[i1], 1);
    g_tok[i1*TT + s1] = t; g_wt[i1*TT + s1] = l[i1];
}

__global__ void aux_k(float* __restrict__ out_aux) {
    float acc = 0.f;
    for (int i = threadIdx.x; i < SS*EE; i += 256) {
        int s = i >> 3, e = i & 7;
        float a = 0.5f*(g_probs[(size_t)s*EE + e] + g_probs[(size_t)(SS+s)*EE + e]);
        float d = 0.125f - a;
        acc += d*d;
    }
    __shared__ float sm[256];
    sm[threadIdx.x] = acc; __syncthreads();
    for (int st = 128; st > 0; st >>= 1) {
        if (threadIdx.x < st) sm[threadIdx.x] += sm[threadIdx.x + st];
        __syncthreads();
    }
    if (threadIdx.x == 0) out_aux[0] = sm[0];
}

// ---------------- x conversion ----------------------------------------------
__device__ __forceinline__ void split1(float v, __nv_bfloat16& h, __nv_bfloat16& l) {
    h = __float2bfloat16(v);
    l = __float2bfloat16(v - __bfloat162float(h));
}

__global__ void splitx_k(const float* __restrict__ x) {
    int i = blockIdx.x*blockDim.x + threadIdx.x;   // i indexes float4
    float4 v = ((const float4*)x)[i];
    __nv_bfloat16 h0,l0,h1,l1,h2,l2,h3,l3;
    split1(v.x,h0,l0); split1(v.y,h1,l1); split1(v.z,h2,l2); split1(v.w,h3,l3);
    __nv_bfloat162* ph = (__nv_bfloat162*)d_xh;
    __nv_bfloat162* pl = (__nv_bfloat162*)d_xl;
    ph[i*2]   = __nv_bfloat162(h0,h1);  ph[i*2+1] = __nv_bfloat162(h2,h3);
    pl[i*2]   = __nv_bfloat162(l0,l1);  pl[i*2+1] = __nv_bfloat162(l2,l3);
}

union BP4 { unsigned long long u; __nv_bfloat16 h[4]; };

// ---------------- GEMM1 (HMMA, double-buffered, 2 CTAs/SM) -------------------
// M=128, N=64 per matrix; K-stage=32.
// smem: ABUF p*16384 (XH+XL 8K each) | BBUF 32768+p*16384 (b1h,b1l,b3h,b3l 4K)
//       | Bf32 STAGE 65536 (16KB, single) | stok 81920
#define G1_AB(p)  ((p)*16384)
#define G1_BB(p)  (32768 + (p)*16384)
#define G1_STAGE  65536
#define G1_SMEM   82432
#define G1_NS     (DD/32)

__global__ __launch_bounds__(256, 2)
void gemm1_k(const float* __restrict__ w1, const float* __restrict__ w3) {
    extern __shared__ char smem[];
    int e = blockIdx.z;
    int cnt = g_count[e];
    int row0 = blockIdx.y * 128;
    if (row0 >= cnt) return;
    int col0 = blockIdx.x * 64;

    int tid = threadIdx.x, wid = tid >> 5, lane = tid & 31;
    uint32_t sb = smem_u32(smem);
    int* stok = (int*)(smem + 81920);

    if (tid < 128) stok[tid] = g_tok[e*TT + min(row0 + tid, cnt-1)];
    __syncthreads();

    int warpM = (wid & 1) * 64;
    int warpN = (wid >> 1) * 16;
    int fr  = (lane & 7) + ((lane >> 3) & 1) * 8;
    int fkb = (lane >> 4) * 16;

    // stage load: A bf16 via cp.async + B fp32 via cp.async (to STAGE)
    auto cpStage = [&](int s) {
        int kk = s*32, p = s & 1;
#pragma unroll
        for (int i = 0; i < 4; i++) {              // A: 1024 chunks
            int g = tid + 256*i;
            int buf = g >> 9, idx = g & 511;
            int row = idx >> 2, c = idx & 3;
            const __nv_bfloat16* src =
                (buf ? d_xl : d_xh) + (size_t)stok[row]*DD + kk + c*8;
            cp16(sb + G1_AB(p) + buf*8192 + SW64(row*64 + c*16), src);
        }
#pragma unroll
        for (int i = 0; i < 4; i++) {              // B fp32: 1024 chunks
            int g = tid + 256*i;
            int mat = g >> 9, idx = g & 511;
            int krow = idx >> 4, nch = idx & 15;
            const float* wp = mat ? w3 : w1;
            cp16(sb + G1_STAGE + mat*8192 + krow*256 + nch*16,
                 wp + ((size_t)(e*DD + kk + krow))*HH + col0 + nch*4);
        }
        CP_COMMIT();
    };
    // convert STAGE fp32 -> BBUF(p) bf16 hi/lo
    auto convB = [&](int p) {
#pragma unroll
        for (int i = 0; i < 4; i++) {
            int g = tid + 256*i;
            int mat = g >> 9, idx = g & 511;
            int krow = idx >> 4, nch = idx & 15;
            float4 v = *(float4*)(smem + G1_STAGE + mat*8192 + krow*256 + nch*16);
            BP4 ph, pl;
            split1(v.x, ph.h[0], pl.h[0]);
            split1(v.y, ph.h[1], pl.h[1]);
            split1(v.z, ph.h[2], pl.h[2]);
            split1(v.w, ph.h[3], pl.h[3]);
            char* base = smem + G1_BB(p) + mat*8192;
            uint32_t off = SW128(krow*128 + nch*8);
            *(unsigned long long*)(base + off)        = ph.u;
            *(unsigned long long*)(base + 4096 + off) = pl.u;
        }
    };

    float c1[4][2][4], c3[4][2][4];
#pragma unroll
    for (int i = 0; i < 4; i++)
#pragma unroll
        for (int j = 0; j < 2; j++)
#pragma unroll
            for (int r = 0; r < 4; r++) { c1[i][j][r] = 0.f; c3[i][j][r] = 0.f; }

    // prologue
    cpStage(0);
    CP_WAIT0();
    __syncthreads();
    convB(0);
    __syncthreads();

    for (int s = 0; s < G1_NS; s++) {
        bool more = (s + 1 < G1_NS);
        if (more) cpStage(s + 1);

        int p = s & 1;
        uint32_t ab = sb + G1_AB(p), bb = sb + G1_BB(p);
#pragma unroll
        for (int k16 = 0; k16 < 2; k16++) {
            uint32_t ah[4][4], al[4][4];
#pragma unroll
            for (int mt = 0; mt < 4; mt++) {
                uint32_t offA = SW64((warpM + mt*16 + fr)*64 + k16*32 + fkb);
                ldsm4(ah[mt][0], ah[mt][1], ah[mt][2], ah[mt][3], ab + offA);
                ldsm4(al[mt][0], al[mt][1], al[mt][2], al[mt][3], ab + 8192 + offA);
            }
            uint32_t offB = SW128((k16*16 + fr)*128 + warpN*2 + fkb);
            uint32_t bh[4], bl[4];
            // w1
            ldsm4t(bh[0], bh[1], bh[2], bh[3], bb + offB);
            ldsm4t(bl[0], bl[1], bl[2], bl[3], bb + 4096 + offB);
#pragma unroll
            for (int mt = 0; mt < 4; mt++)
#pragma unroll
                for (int nt = 0; nt < 2; nt++) {
                    mma16816(c1[mt][nt], ah[mt][0],ah[mt][1],ah[mt][2],ah[mt][3], bh[nt*2], bh[nt*2+1]);
                    mma16816(c1[mt][nt], al[mt][0],al[mt][1],al[mt][2],al[mt][3], bh[nt*2], bh[nt*2+1]);
                    mma16816(c1[mt][nt], ah[mt][0],ah[mt][1],ah[mt][2],ah[mt][3], bl[nt*2], bl[nt*2+1]);
                }
            // w3 (reuse b frag regs)
            ldsm4t(bh[0], bh[1], bh[2], bh[3], bb + 8192 + offB);
            ldsm4t(bl[0], bl[1], bl[2], bl[3], bb + 12288 + offB);
#pragma unroll
            for (int mt = 0; mt < 4; mt++)
#pragma unroll
                for (int nt = 0; nt < 2; nt++) {
                    mma16816(c3[mt][nt], ah[mt][0],ah[mt][1],ah[mt][2],ah[mt][3], bh[nt*2], bh[nt*2+1]);
                    mma16816(c3[mt][nt], al[mt][0],al[mt][1],al[mt][2],al[mt][3], bh[nt*2], bh[nt*2+1]);
                    mma16816(c3[mt][nt], ah[mt][0],ah[mt][1],ah[mt][2],ah[mt][3], bl[nt*2], bl[nt*2+1]);
                }
        }

        if (more) {
            CP_WAIT0();
            __syncthreads();
            convB((s + 1) & 1);
            __syncthreads();
        }
    }

    // epilogue
#pragma unroll
    for (int mt = 0; mt < 4; mt++) {
#pragma unroll
        for (int half = 0; half < 2; half++) {
            int rg = row0 + warpM + mt*16 + (lane >> 2) + half*8;
            if (rg < cnt) {
                size_t rowi = (size_t)(e*TT + rg);
                size_t cb = col0 + warpN + (lane & 3)*2;
#pragma unroll
                for (int nt = 0; nt < 2; nt++) {
                    float s0 = c1[mt][nt][half*2],   g0 = c3[mt][nt][half*2];
                    float s1 = c1[mt][nt][half*2+1], g1 = c3[mt][nt][half*2+1];
                    float v0 = __sinf(s0)*g0, v1 = __sinf(s1)*g1;
                    __nv_bfloat16 h0,l0,h1,l1;
                    split1(v0,h0,l0); split1(v1,h1,l1);
                    *(__nv_bfloat162*)(d_h2 + (rowi*2)*HH   + cb + nt*8) = __nv_bfloat162(h0,h1);
                    *(__nv_bfloat162*)(d_h2 + (rowi*2+1)*HH + cb + nt*8) = __nv_bfloat162(l0,l1);
                }
            }
        }
    }
}

// ---------------- GEMM2 (HMMA, double-buffered, 2 CTAs/SM) -------------------
// smem: ABUF p*16384 (AH+AL) | BBUF 32768+p*8192 (w2h,w2l 4K) |
//       STAGE 49152 (8KB) | ctrl 57344
#define G2_AB(p)  ((p)*16384)
#define G2_BB(p)  (32768 + (p)*8192)
#define G2_STAGE  49152
#define G2_SMEM   58368
#define G2_NS     (HH/32)

__global__ __launch_bounds__(256, 2)
void gemm2_k(const float* __restrict__ w2, float* __restrict__ out) {
    extern __shared__ char smem[];
    int e = blockIdx.z;
    int cnt = g_count[e];
    int row0 = blockIdx.y * 128;
    if (row0 >= cnt) return;
    int col0 = blockIdx.x * 64;

    int tid = threadIdx.x, wid = tid >> 5, lane = tid & 31;
    uint32_t sb = smem_u32(smem);
    int*   stok = (int*)(smem + 57344);
    float* swt  = (float*)(smem + 57344 + 512);

    if (tid < 128) {
        int r = min(row0 + tid, cnt-1);
        stok[tid] = g_tok[e*TT + r];
        swt[tid]  = g_wt[e*TT + r];
    }
    __syncthreads();

    int warpM = (wid & 1) * 64;
    int warpN = (wid >> 1) * 16;
    int fr  = (lane & 7) + ((lane >> 3) & 1) * 8;
    int fkb = (lane >> 4) * 16;
    size_t arow0 = (size_t)(e*TT + row0);

    auto cpStage = [&](int s) {
        int kk = s*32, p = s & 1;
#pragma unroll
        for (int i = 0; i < 4; i++) {              // A: 1024 chunks
            int g = tid + 256*i;
            int buf = g >> 9, idx = g & 511;
            int row = idx >> 2, c = idx & 3;
            const __nv_bfloat16* src =
                d_h2 + ((arow0 + row)*2 + buf)*HH + kk + c*8;
            cp16(sb + G2_AB(p) + buf*8192 + SW64(row*64 + c*16), src);
        }
#pragma unroll
        for (int i = 0; i < 2; i++) {              // B fp32: 512 chunks
            int g = tid + 256*i;
            int krow = g >> 4, nch = g & 15;
            cp16(sb + G2_STAGE + krow*256 + nch*16,
                 w2 + ((size_t)(e*HH + kk + krow))*DD + col0 + nch*4);
        }
        CP_COMMIT();
    };
    auto convB = [&](int p) {
#pragma unroll
        for (int i = 0; i < 2; i++) {
            int g = tid + 256*i;
            int krow = g >> 4, nch = g & 15;
            float4 v = *(float4*)(smem + G2_STAGE + krow*256 + nch*16);
            BP4 ph, pl;
            split1(v.x, ph.h[0], pl.h[0]);
            split1(v.y, ph.h[1], pl.h[1]);
            split1(v.z, ph.h[2], pl.h[2]);
            split1(v.w, ph.h[3], pl.h[3]);
            char* base = smem + G2_BB(p);
            uint32_t off = SW128(krow*128 + nch*8);
            *(unsigned long long*)(base + off)        = ph.u;
            *(unsigned long long*)(base + 4096 + off) = pl.u;
        }
    };

    float cc[4][2][4];
#pragma unroll
    for (int i = 0; i < 4; i++)
#pragma unroll
        for (int j = 0; j < 2; j++)
#pragma unroll
            for (int r = 0; r < 4; r++) cc[i][j][r] = 0.f;

    cpStage(0);
    CP_WAIT0();
    __syncthreads();
    convB(0);
    __syncthreads();

    for (int s = 0; s < G2_NS; s++) {
        bool more = (s + 1 < G2_NS);
        if (more) cpStage(s + 1);

        int p = s & 1;
        uint32_t ab = sb + G2_AB(p), bb = sb + G2_BB(p);
#pragma unroll
        for (int k16 = 0; k16 < 2; k16++) {
            uint32_t ah[4][4], al[4][4];
#pragma unroll
            for (int mt = 0; mt < 4; mt++) {
                uint32_t offA = SW64((warpM + mt*16 + fr)*64 + k16*32 + fkb);
                ldsm4(ah[mt][0], ah[mt][1], ah[mt][2], ah[mt][3], ab + offA);
                ldsm4(al[mt][0], al[mt][1], al[mt][2], al[mt][3], ab + 8192 + offA);
            }
            uint32_t offB = SW128((k16*16 + fr)*128 + warpN*2 + fkb);
            uint32_t bh[4], bl[4];
            ldsm4t(bh[0], bh[1], bh[2], bh[3], bb + offB);
            ldsm4t(bl[0], bl[1], bl[2], bl[3], bb + 4096 + offB);
#pragma unroll
            for (int mt = 0; mt < 4; mt++)
#pragma unroll
                for (int nt = 0; nt < 2; nt++) {
                    mma16816(cc[mt][nt], ah[mt][0],ah[mt][1],ah[mt][2],ah[mt][3], bh[nt*2], bh[nt*2+1]);
                    mma16816(cc[mt][nt], al[mt][0],al[mt][1],al[mt][2],al[mt][3], bh[nt*2], bh[nt*2+1]);
                    mma16816(cc[mt][nt], ah[mt][0],ah[mt][1],ah[mt][2],ah[mt][3], bl[nt*2], bl[nt*2+1]);
                }
        }

        if (more) {
            CP_WAIT0();
            __syncthreads();
            convB((s + 1) & 1);
            __syncthreads();
        }
    }

    // epilogue: weighted atomic scatter
#pragma unroll
    for (int mt = 0; mt < 4; mt++) {
#pragma unroll
        for (int half = 0; half < 2; half++) {
            int ml = warpM + mt*16 + (lane >> 2) + half*8;
            if (row0 + ml < cnt) {
                int   tok = stok[ml];
                float wt  = swt[ml];
                float* op = out + (size_t)tok*DD + col0 + warpN + (lane & 3)*2;
#pragma unroll
                for (int nt = 0; nt < 2; nt++) {
                    atomicAdd(op + nt*8 + 0, wt * cc[mt][nt][half*2]);
                    atomicAdd(op + nt*8 + 1, wt * cc[mt][nt][half*2+1]);
                }
            }
        }
    }
}

// ---------------- launch -----------------------------------------------------
extern "C" void kernel_launch(void* const* d_in, const int* in_sizes, int n_in,
                              void* d_out, int out_size) {
    const float* x  = (const float*)d_in[0];
    const float* w1 = (const float*)d_in[1];
    const float* w2 = (const float*)d_in[2];
    const float* w3 = (const float*)d_in[3];
    const float* rw = (const float*)d_in[4];
    const float* rb = (const float*)d_in[5];
    float* out = (float*)d_out;

    // host-side config (called every launch; no static guard)
    cudaFuncSetAttribute(gemm1_k, cudaFuncAttributeMaxDynamicSharedMemorySize, G1_SMEM);
    cudaFuncSetAttribute(gemm2_k, cudaFuncAttributeMaxDynamicSharedMemorySize, G2_SMEM);

    cudaMemsetAsync(d_out, 0, (size_t)out_size * sizeof(float));

    init_k<<<1, 32>>>();
    router_k<<<TT, 128>>>(x, rw, rb);
    norm_k<<<BB*EE, 256>>>();
    route_k<<<TT/256, 256>>>();
    if (out_size > TT*DD) aux_k<<<1, 256>>>(out + (size_t)TT*DD);

    splitx_k<<<TT*DD/1024, 256>>>(x);

    gemm1_k<<<dim3(HH/64, TT/128, EE), 256, G1_SMEM>>>(w1, w3);
    gemm2_k<<<dim3(DD/64, TT/128, EE), 256, G2_SMEM>>>(w2, out);
}

// round 9
// speedup vs baseline: 2.5264x; 1.0247x over previous
#include <cuda_runtime.h>
#include <cuda_bf16.h>
#include <math.h>
#include <cstdint>

#define BB 2
#define SS 2048
#define DD 1024
#define HH 2816
#define EE 8
#define TT (BB*SS)

// ---------------- scratch (device globals; total ~386MB — proven safe) ------
__device__ float g_logits[TT*EE];
__device__ float g_probs [TT*EE];
__device__ float g_nrm   [BB*EE];
__device__ int   g_count [EE];
__device__ int   g_tok   [EE*TT];
__device__ float g_wt    [EE*TT];

__device__ __align__(256) __nv_bfloat16 d_xh[TT*DD], d_xl[TT*DD];     // 16.8MB
// H hi/lo interleaved: row (e*TT+r) -> hi at (row*2)*HH, lo at (row*2+1)*HH
__device__ __align__(256) __nv_bfloat16 d_h2[(size_t)EE*TT*2*HH];     // 369MB

// ---------------- PTX helpers ------------------------------------------------
__device__ __forceinline__ uint32_t smem_u32(const void* p) {
    uint32_t a;
    asm("{ .reg .u64 t; cvta.to.shared.u64 t, %1; cvt.u32.u64 %0, t; }"
        : "=r"(a) : "l"(p));
    return a;
}
#define SW64(o)  ((uint32_t)(o) ^ ((((uint32_t)(o)) >> 3) & 0x30))
#define SW128(o) ((uint32_t)(o) ^ ((((uint32_t)(o)) >> 3) & 0x70))

__device__ __forceinline__ void cp16(uint32_t dst, const void* src) {
    asm volatile("cp.async.cg.shared.global [%0], [%1], 16;"
                 :: "r"(dst), "l"(__cvta_generic_to_global(src)) : "memory");
}
#define CP_COMMIT() asm volatile("cp.async.commit_group;" ::: "memory")
#define CP_WAIT0()  asm volatile("cp.async.wait_group 0;" ::: "memory")

__device__ __forceinline__ void ldsm4(uint32_t& r0, uint32_t& r1,
                                      uint32_t& r2, uint32_t& r3, uint32_t a) {
    asm volatile("ldmatrix.sync.aligned.m8n8.x4.shared.b16 {%0,%1,%2,%3}, [%4];"
                 : "=r"(r0), "=r"(r1), "=r"(r2), "=r"(r3) : "r"(a));
}
__device__ __forceinline__ void ldsm4t(uint32_t& r0, uint32_t& r1,
                                       uint32_t& r2, uint32_t& r3, uint32_t a) {
    asm volatile("ldmatrix.sync.aligned.m8n8.x4.trans.shared.b16 {%0,%1,%2,%3}, [%4];"
                 : "=r"(r0), "=r"(r1), "=r"(r2), "=r"(r3) : "r"(a));
}
__device__ __forceinline__ void mma16816(float* c,
        uint32_t a0, uint32_t a1, uint32_t a2, uint32_t a3,
        uint32_t b0, uint32_t b1) {
    asm volatile("mma.sync.aligned.m16n8k16.row.col.f32.bf16.bf16.f32 "
        "{%0,%1,%2,%3},{%4,%5,%6,%7},{%8,%9},{%0,%1,%2,%3};"
        : "+f"(c[0]), "+f"(c[1]), "+f"(c[2]), "+f"(c[3])
        : "r"(a0), "r"(a1), "r"(a2), "r"(a3), "r"(b0), "r"(b1));
}

__device__ __forceinline__ void split1(float v, __nv_bfloat16& h, __nv_bfloat16& l) {
    h = __float2bfloat16(v);
    l = __float2bfloat16(v - __bfloat162float(h));
}

union BP4 { unsigned long long u; __nv_bfloat16 h[4]; };

// ---------------- router + x-split fused (1st kernel) ------------------------
__global__ void router_k(const float* __restrict__ x,
                         const float* __restrict__ rw,
                         const float* __restrict__ rb) {
    int t = blockIdx.x;
    if (t == 0 && threadIdx.x < EE) g_count[threadIdx.x] = 0;

    // ---- splitx part: this block handles token t's 256 float4 (2/thread) ----
    {
        const float4* xr4 = (const float4*)(x + (size_t)t * DD);
        __nv_bfloat162* ph = (__nv_bfloat162*)(d_xh + (size_t)t * DD);
        __nv_bfloat162* pl = (__nv_bfloat162*)(d_xl + (size_t)t * DD);
#pragma unroll
        for (int i = 0; i < 2; i++) {
            int j = threadIdx.x + 128*i;
            float4 v = xr4[j];
            __nv_bfloat16 h0,l0,h1,l1,h2,l2,h3,l3;
            split1(v.x,h0,l0); split1(v.y,h1,l1);
            split1(v.z,h2,l2); split1(v.w,h3,l3);
            ph[j*2]   = __nv_bfloat162(h0,h1);  ph[j*2+1] = __nv_bfloat162(h2,h3);
            pl[j*2]   = __nv_bfloat162(l0,l1);  pl[j*2+1] = __nv_bfloat162(l2,l3);
        }
    }

    // ---- router part (verbatim R1) ----
    const float* xr = x + (size_t)t * DD;
    float acc[EE];
#pragma unroll
    for (int e = 0; e < EE; e++) acc[e] = 0.f;
    for (int d = threadIdx.x; d < DD; d += 128) {
        float xv = xr[d];
        const float4* r = (const float4*)(rw + (size_t)d * EE);
        float4 r0 = r[0], r1 = r[1];
        acc[0] += xv*r0.x; acc[1] += xv*r0.y; acc[2] += xv*r0.z; acc[3] += xv*r0.w;
        acc[4] += xv*r1.x; acc[5] += xv*r1.y; acc[6] += xv*r1.z; acc[7] += xv*r1.w;
    }
    __shared__ float sm[EE][128];
#pragma unroll
    for (int e = 0; e < EE; e++) sm[e][threadIdx.x] = acc[e];
    __syncthreads();
    for (int s = 64; s > 0; s >>= 1) {
        if (threadIdx.x < s)
#pragma unroll
            for (int e = 0; e < EE; e++) sm[e][threadIdx.x] += sm[e][threadIdx.x + s];
        __syncthreads();
    }
    if (threadIdx.x < EE)
        g_logits[(size_t)t*EE + threadIdx.x] = sm[threadIdx.x][0] + rb[threadIdx.x];
}

__global__ void norm_k() {
    int b = blockIdx.x >> 3, e = blockIdx.x & 7;
    float s = 0.f;
    for (int i = threadIdx.x; i < SS; i += 256) {
        float v = g_logits[((size_t)(b*SS + i))*EE + e];
        s += v*v;
    }
    __shared__ float sm[256];
    sm[threadIdx.x] = s; __syncthreads();
    for (int st = 128; st > 0; st >>= 1) {
        if (threadIdx.x < st) sm[threadIdx.x] += sm[threadIdx.x + st];
        __syncthreads();
    }
    if (threadIdx.x == 0) g_nrm[blockIdx.x] = fmaxf(sqrtf(sm[0]), 1e-12f);
}

__global__ void route_k() {
    int t = blockIdx.x*blockDim.x + threadIdx.x;
    if (t >= TT) return;
    int b = t / SS;
    float l[EE]; float m = -1e30f;
#pragma unroll
    for (int e = 0; e < EE; e++) {
        l[e] = g_logits[(size_t)t*EE + e] / g_nrm[b*EE + e];
        m = fmaxf(m, l[e]);
    }
    float sum = 0.f;
#pragma unroll
    for (int e = 0; e < EE; e++) { l[e] = expf(l[e]-m); sum += l[e]; }
    float inv = 1.f/sum;
#pragma unroll
    for (int e = 0; e < EE; e++) { l[e] *= inv; g_probs[(size_t)t*EE + e] = l[e]; }
    int i0 = 0;
#pragma unroll
    for (int e = 1; e < EE; e++) if (l[e] > l[i0]) i0 = e;
    int i1 = -1;
#pragma unroll
    for (int e = 0; e < EE; e++) {
        if (e == i0) continue;
        if (i1 < 0 || l[e] > l[i1]) i1 = e;
    }
    int s0 = atomicAdd(&g_count[i0], 1);
    g_tok[i0*TT + s0] = t; g_wt[i0*TT + s0] = l[i0];
    int s1 = atomicAdd(&g_count[i1], 1);
    g_tok[i1*TT + s1] = t; g_wt[i1*TT + s1] = l[i1];
}

__global__ void aux_k(float* __restrict__ out_aux) {
    float acc = 0.f;
    for (int i = threadIdx.x; i < SS*EE; i += 256) {
        int s = i >> 3, e = i & 7;
        float a = 0.5f*(g_probs[(size_t)s*EE + e] + g_probs[(size_t)(SS+s)*EE + e]);
        float d = 0.125f - a;
        acc += d*d;
    }
    __shared__ float sm[256];
    sm[threadIdx.x] = acc; __syncthreads();
    for (int st = 128; st > 0; st >>= 1) {
        if (threadIdx.x < st) sm[threadIdx.x] += sm[threadIdx.x + st];
        __syncthreads();
    }
    if (threadIdx.x == 0) out_aux[0] = sm[0];
}

// ---------------- GEMM1 (HMMA, 1-sync pipelined, 2 CTAs/SM) ------------------
// M=128, N=64 per matrix; K-stage=32.
// smem: AB(p)=p*16384 (XH+XL 8K) | BB(p)=32768+p*16384 (b1h,b1l,b3h,b3l 4K)
//       STAGE(q)=65536+q*16384 (fp32 B both mats, 16K) | stok 98304
#define G1_AB(p)  ((p)*16384)
#define G1_BB(p)  (32768 + (p)*16384)
#define G1_ST(q)  (65536 + (q)*16384)
#define G1_SMEM   98816
#define G1_NS     (DD/32)

__global__ __launch_bounds__(256, 2)
void gemm1_k(const float* __restrict__ w1, const float* __restrict__ w3) {
    extern __shared__ char smem[];
    int e = blockIdx.z;
    int cnt = g_count[e];
    int row0 = blockIdx.y * 128;
    if (row0 >= cnt) return;
    int col0 = blockIdx.x * 64;

    int tid = threadIdx.x, wid = tid >> 5, lane = tid & 31;
    uint32_t sb = smem_u32(smem);
    int* stok = (int*)(smem + 98304);

    if (tid < 128) stok[tid] = g_tok[e*TT + min(row0 + tid, cnt-1)];
    __syncthreads();

    int warpM = (wid & 1) * 64;
    int warpN = (wid >> 1) * 16;
    int fr  = (lane & 7) + ((lane >> 3) & 1) * 8;
    int fkb = (lane >> 4) * 16;

    auto cpA = [&](int s) {               // -> AB(s&1)
        int kk = s*32;
        uint32_t base = sb + G1_AB(s & 1);
#pragma unroll
        for (int i = 0; i < 4; i++) {
            int g = tid + 256*i;
            int buf = g >> 9, idx = g & 511;
            int row = idx >> 2, c = idx & 3;
            const __nv_bfloat16* src =
                (buf ? d_xl : d_xh) + (size_t)stok[row]*DD + kk + c*8;
            cp16(base + buf*8192 + SW64(row*64 + c*16), src);
        }
    };
    auto cpB32 = [&](int s) {             // -> STAGE(s&1)
        int kk = s*32;
        uint32_t base = sb + G1_ST(s & 1);
#pragma unroll
        for (int i = 0; i < 4; i++) {
            int g = tid + 256*i;
            int mat = g >> 9, idx = g & 511;
            int krow = idx >> 4, nch = idx & 15;
            const float* wp = mat ? w3 : w1;
            cp16(base + mat*8192 + krow*256 + nch*16,
                 wp + ((size_t)(e*DD + kk + krow))*HH + col0 + nch*4);
        }
    };
    auto convB = [&](int j) {             // STAGE(j&1) -> BB(j&1)
        char* src = smem + G1_ST(j & 1);
        char* dst = smem + G1_BB(j & 1);
#pragma unroll
        for (int i = 0; i < 4; i++) {
            int g = tid + 256*i;
            int mat = g >> 9, idx = g & 511;
            int krow = idx >> 4, nch = idx & 15;
            float4 v = *(float4*)(src + mat*8192 + krow*256 + nch*16);
            BP4 ph, pl;
            split1(v.x, ph.h[0], pl.h[0]);
            split1(v.y, ph.h[1], pl.h[1]);
            split1(v.z, ph.h[2], pl.h[2]);
            split1(v.w, ph.h[3], pl.h[3]);
            uint32_t off = SW128(krow*128 + nch*8);
            *(unsigned long long*)(dst + mat*8192 + off)        = ph.u;
            *(unsigned long long*)(dst + mat*8192 + 4096 + off) = pl.u;
        }
    };

    float c1[4][2][4], c3[4][2][4];
#pragma unroll
    for (int i = 0; i < 4; i++)
#pragma unroll
        for (int j = 0; j < 2; j++)
#pragma unroll
            for (int r = 0; r < 4; r++) { c1[i][j][r] = 0.f; c3[i][j][r] = 0.f; }

    // prologue: A(0), Bf32(0), Bf32(1); conv B(0)
    cpA(0); cpB32(0); cpB32(1); CP_COMMIT();
    CP_WAIT0(); __syncthreads();
    convB(0);
    __syncthreads();

    for (int s = 0; s < G1_NS; s++) {
        int p = s & 1;
        if (s + 1 < G1_NS) cpA(s + 1);
        if (s + 2 < G1_NS) cpB32(s + 2);
        CP_COMMIT();
        if (s + 1 < G1_NS) convB(s + 1);   // overlaps with MMA below

        uint32_t ab = sb + G1_AB(p), bb = sb + G1_BB(p);
#pragma unroll
        for (int k16 = 0; k16 < 2; k16++) {
            uint32_t ah[4][4], al[4][4];
#pragma unroll
            for (int mt = 0; mt < 4; mt++) {
                uint32_t offA = SW64((warpM + mt*16 + fr)*64 + k16*32 + fkb);
                ldsm4(ah[mt][0], ah[mt][1], ah[mt][2], ah[mt][3], ab + offA);
                ldsm4(al[mt][0], al[mt][1], al[mt][2], al[mt][3], ab + 8192 + offA);
            }
            uint32_t offB = SW128((k16*16 + fr)*128 + warpN*2 + fkb);
            uint32_t bh[4], bl[4];
            // w1
            ldsm4t(bh[0], bh[1], bh[2], bh[3], bb + offB);
            ldsm4t(bl[0], bl[1], bl[2], bl[3], bb + 4096 + offB);
#pragma unroll
            for (int mt = 0; mt < 4; mt++)
#pragma unroll
                for (int nt = 0; nt < 2; nt++) {
                    mma16816(c1[mt][nt], ah[mt][0],ah[mt][1],ah[mt][2],ah[mt][3], bh[nt*2], bh[nt*2+1]);
                    mma16816(c1[mt][nt], al[mt][0],al[mt][1],al[mt][2],al[mt][3], bh[nt*2], bh[nt*2+1]);
                    mma16816(c1[mt][nt], ah[mt][0],ah[mt][1],ah[mt][2],ah[mt][3], bl[nt*2], bl[nt*2+1]);
                }
            // w3
            ldsm4t(bh[0], bh[1], bh[2], bh[3], bb + 8192 + offB);
            ldsm4t(bl[0], bl[1], bl[2], bl[3], bb + 12288 + offB);
#pragma unroll
            for (int mt = 0; mt < 4; mt++)
#pragma unroll
                for (int nt = 0; nt < 2; nt++) {
                    mma16816(c3[mt][nt], ah[mt][0],ah[mt][1],ah[mt][2],ah[mt][3], bh[nt*2], bh[nt*2+1]);
                    mma16816(c3[mt][nt], al[mt][0],al[mt][1],al[mt][2],al[mt][3], bh[nt*2], bh[nt*2+1]);
                    mma16816(c3[mt][nt], ah[mt][0],ah[mt][1],ah[mt][2],ah[mt][3], bl[nt*2], bl[nt*2+1]);
                }
        }

        if (s + 1 < G1_NS) { CP_WAIT0(); __syncthreads(); }
    }

    // epilogue
#pragma unroll
    for (int mt = 0; mt < 4; mt++) {
#pragma unroll
        for (int half = 0; half < 2; half++) {
            int rg = row0 + warpM + mt*16 + (lane >> 2) + half*8;
            if (rg < cnt) {
                size_t rowi = (size_t)(e*TT + rg);
                size_t cb = col0 + warpN + (lane & 3)*2;
#pragma unroll
                for (int nt = 0; nt < 2; nt++) {
                    float s0 = c1[mt][nt][half*2],   g0 = c3[mt][nt][half*2];
                    float s1 = c1[mt][nt][half*2+1], g1 = c3[mt][nt][half*2+1];
                    float v0 = __sinf(s0)*g0, v1 = __sinf(s1)*g1;
                    __nv_bfloat16 h0,l0,h1,l1;
                    split1(v0,h0,l0); split1(v1,h1,l1);
                    *(__nv_bfloat162*)(d_h2 + (rowi*2)*HH   + cb + nt*8) = __nv_bfloat162(h0,h1);
                    *(__nv_bfloat162*)(d_h2 + (rowi*2+1)*HH + cb + nt*8) = __nv_bfloat162(l0,l1);
                }
            }
        }
    }
}

// ---------------- GEMM2 (HMMA, 1-sync pipelined, 2 CTAs/SM) ------------------
// smem: AB(p)=p*16384 (AH+AL) | BB(p)=32768+p*8192 (w2h,w2l 4K)
//       STAGE(q)=49152+q*8192 | ctrl 65536
#define G2_AB(p)  ((p)*16384)
#define G2_BB(p)  (32768 + (p)*8192)
#define G2_ST(q)  (49152 + (q)*8192)
#define G2_SMEM   66560
#define G2_NS     (HH/32)

__global__ __launch_bounds__(256, 2)
void gemm2_k(const float* __restrict__ w2, float* __restrict__ out) {
    extern __shared__ char smem[];
    int e = blockIdx.z;
    int cnt = g_count[e];
    int row0 = blockIdx.y * 128;
    if (row0 >= cnt) return;
    int col0 = blockIdx.x * 64;

    int tid = threadIdx.x, wid = tid >> 5, lane = tid & 31;
    uint32_t sb = smem_u32(smem);
    int*   stok = (int*)(smem + 65536);
    float* swt  = (float*)(smem + 65536 + 512);

    if (tid < 128) {
        int r = min(row0 + tid, cnt-1);
        stok[tid] = g_tok[e*TT + r];
        swt[tid]  = g_wt[e*TT + r];
    }
    __syncthreads();

    int warpM = (wid & 1) * 64;
    int warpN = (wid >> 1) * 16;
    int fr  = (lane & 7) + ((lane >> 3) & 1) * 8;
    int fkb = (lane >> 4) * 16;
    size_t arow0 = (size_t)(e*TT + row0);

    auto cpA = [&](int s) {
        int kk = s*32;
        uint32_t base = sb + G2_AB(s & 1);
#pragma unroll
        for (int i = 0; i < 4; i++) {
            int g = tid + 256*i;
            int buf = g >> 9, idx = g & 511;
            int row = idx >> 2, c = idx & 3;
            const __nv_bfloat16* src =
                d_h2 + ((arow0 + row)*2 + buf)*HH + kk + c*8;
            cp16(base + buf*8192 + SW64(row*64 + c*16), src);
        }
    };
    auto cpB32 = [&](int s) {
        int kk = s*32;
        uint32_t base = sb + G2_ST(s & 1);
#pragma unroll
        for (int i = 0; i < 2; i++) {
            int g = tid + 256*i;
            int krow = g >> 4, nch = g & 15;
            cp16(base + krow*256 + nch*16,
                 w2 + ((size_t)(e*HH + kk + krow))*DD + col0 + nch*4);
        }
    };
    auto convB = [&](int j) {
        char* src = smem + G2_ST(j & 1);
        char* dst = smem + G2_BB(j & 1);
#pragma unroll
        for (int i = 0; i < 2; i++) {
            int g = tid + 256*i;
            int krow = g >> 4, nch = g & 15;
            float4 v = *(float4*)(src + krow*256 + nch*16);
            BP4 ph, pl;
            split1(v.x, ph.h[0], pl.h[0]);
            split1(v.y, ph.h[1], pl.h[1]);
            split1(v.z, ph.h[2], pl.h[2]);
            split1(v.w, ph.h[3], pl.h[3]);
            uint32_t off = SW128(krow*128 + nch*8);
            *(unsigned long long*)(dst + off)        = ph.u;
            *(unsigned long long*)(dst + 4096 + off) = pl.u;
        }
    };

    float cc[4][2][4];
#pragma unroll
    for (int i = 0; i < 4; i++)
#pragma unroll
        for (int j = 0; j < 2; j++)
#pragma unroll
            for (int r = 0; r < 4; r++) cc[i][j][r] = 0.f;

    cpA(0); cpB32(0); cpB32(1); CP_COMMIT();
    CP_WAIT0(); __syncthreads();
    convB(0);
    __syncthreads();

    for (int s = 0; s < G2_NS; s++) {
        int p = s & 1;
        if (s + 1 < G2_NS) cpA(s + 1);
        if (s + 2 < G2_NS) cpB32(s + 2);
        CP_COMMIT();
        if (s + 1 < G2_NS) convB(s + 1);

        uint32_t ab = sb + G2_AB(p), bb = sb + G2_BB(p);
#pragma unroll
        for (int k16 = 0; k16 < 2; k16++) {
            uint32_t ah[4][4], al[4][4];
#pragma unroll
            for (int mt = 0; mt < 4; mt++) {
                uint32_t offA = SW64((warpM + mt*16 + fr)*64 + k16*32 + fkb);
                ldsm4(ah[mt][0], ah[mt][1], ah[mt][2], ah[mt][3], ab + offA);
                ldsm4(al[mt][0], al[mt][1], al[mt][2], al[mt][3], ab + 8192 + offA);
            }
            uint32_t offB = SW128((k16*16 + fr)*128 + warpN*2 + fkb);
            uint32_t bh[4], bl[4];
            ldsm4t(bh[0], bh[1], bh[2], bh[3], bb + offB);
            ldsm4t(bl[0], bl[1], bl[2], bl[3], bb + 4096 + offB);
#pragma unroll
            for (int mt = 0; mt < 4; mt++)
#pragma unroll
                for (int nt = 0; nt < 2; nt++) {
                    mma16816(cc[mt][nt], ah[mt][0],ah[mt][1],ah[mt][2],ah[mt][3], bh[nt*2], bh[nt*2+1]);
                    mma16816(cc[mt][nt], al[mt][0],al[mt][1],al[mt][2],al[mt][3], bh[nt*2], bh[nt*2+1]);
                    mma16816(cc[mt][nt], ah[mt][0],ah[mt][1],ah[mt][2],ah[mt][3], bl[nt*2], bl[nt*2+1]);
                }
        }

        if (s + 1 < G2_NS) { CP_WAIT0(); __syncthreads(); }
    }

    // epilogue: weighted atomic scatter
#pragma unroll
    for (int mt = 0; mt < 4; mt++) {
#pragma unroll
        for (int half = 0; half < 2; half++) {
            int ml = warpM + mt*16 + (lane >> 2) + half*8;
            if (row0 + ml < cnt) {
                int   tok = stok[ml];
                float wt  = swt[ml];
                float* op = out + (size_t)tok*DD + col0 + warpN + (lane & 3)*2;
#pragma unroll
                for (int nt = 0; nt < 2; nt++) {
                    atomicAdd(op + nt*8 + 0, wt * cc[mt][nt][half*2]);
                    atomicAdd(op + nt*8 + 1, wt * cc[mt][nt][half*2+1]);
                }
            }
        }
    }
}

// ---------------- launch -----------------------------------------------------
extern "C" void kernel_launch(void* const* d_in, const int* in_sizes, int n_in,
                              void* d_out, int out_size) {
    const float* x  = (const float*)d_in[0];
    const float* w1 = (const float*)d_in[1];
    const float* w2 = (const float*)d_in[2];
    const float* w3 = (const float*)d_in[3];
    const float* rw = (const float*)d_in[4];
    const float* rb = (const float*)d_in[5];
    float* out = (float*)d_out;

    cudaFuncSetAttribute(gemm1_k, cudaFuncAttributeMaxDynamicSharedMemorySize, G1_SMEM);
    cudaFuncSetAttribute(gemm2_k, cudaFuncAttributeMaxDynamicSharedMemorySize, G2_SMEM);

    cudaMemsetAsync(d_out, 0, (size_t)out_size * sizeof(float));

    router_k<<<TT, 128>>>(x, rw, rb);                       // kernel 1 (+split+init)
    norm_k<<<BB*EE, 256>>>();                               // kernel 2
    route_k<<<TT/256, 256>>>();                             // kernel 3
    gemm1_k<<<dim3(HH/64, TT/128, EE), 256, G1_SMEM>>>(w1, w3);   // kernel 4 (ncu)
    gemm2_k<<<dim3(DD/64, TT/128, EE), 256, G2_SMEM>>>(w2, out);  // kernel 5
    if (out_size > TT*DD) aux_k<<<1, 256>>>(out + (size_t)TT*DD); // kernel 6
}

// round 10
// speedup vs baseline: 2.5810x; 1.0216x over previous
#include <cuda_runtime.h>
#include <cuda_bf16.h>
#include <math.h>
#include <cstdint>

#define BB 2
#define SS 2048
#define DD 1024
#define HH 2816
#define EE 8
#define TT (BB*SS)

// ---------------- scratch (device globals; total ~386MB — proven safe) ------
__device__ float g_logits[TT*EE];
__device__ float g_probs [TT*EE];
__device__ float g_nrm   [BB*EE];
__device__ int   g_count [EE];
__device__ int   g_tok   [EE*TT];
__device__ float g_wt    [EE*TT];

__device__ __align__(256) __nv_bfloat16 d_xh[TT*DD], d_xl[TT*DD];     // 16.8MB
// H hi/lo interleaved: row (e*TT+r) -> hi at (row*2)*HH, lo at (row*2+1)*HH
__device__ __align__(256) __nv_bfloat16 d_h2[(size_t)EE*TT*2*HH];     // 369MB

// ---------------- PTX helpers ------------------------------------------------
__device__ __forceinline__ uint32_t smem_u32(const void* p) {
    uint32_t a;
    asm("{ .reg .u64 t; cvta.to.shared.u64 t, %1; cvt.u32.u64 %0, t; }"
        : "=r"(a) : "l"(p));
    return a;
}
#define SW64(o)  ((uint32_t)(o) ^ ((((uint32_t)(o)) >> 3) & 0x30))
#define SW128(o) ((uint32_t)(o) ^ ((((uint32_t)(o)) >> 3) & 0x70))

__device__ __forceinline__ void cp16(uint32_t dst, const void* src) {
    asm volatile("cp.async.cg.shared.global [%0], [%1], 16;"
                 :: "r"(dst), "l"(__cvta_generic_to_global(src)) : "memory");
}
#define CP_COMMIT() asm volatile("cp.async.commit_group;" ::: "memory")
#define CP_WAIT0()  asm volatile("cp.async.wait_group 0;" ::: "memory")

__device__ __forceinline__ void ldsm4(uint32_t& r0, uint32_t& r1,
                                      uint32_t& r2, uint32_t& r3, uint32_t a) {
    asm volatile("ldmatrix.sync.aligned.m8n8.x4.shared.b16 {%0,%1,%2,%3}, [%4];"
                 : "=r"(r0), "=r"(r1), "=r"(r2), "=r"(r3) : "r"(a));
}
__device__ __forceinline__ void ldsm4t(uint32_t& r0, uint32_t& r1,
                                       uint32_t& r2, uint32_t& r3, uint32_t a) {
    asm volatile("ldmatrix.sync.aligned.m8n8.x4.trans.shared.b16 {%0,%1,%2,%3}, [%4];"
                 : "=r"(r0), "=r"(r1), "=r"(r2), "=r"(r3) : "r"(a));
}
__device__ __forceinline__ void mma16816(float* c,
        uint32_t a0, uint32_t a1, uint32_t a2, uint32_t a3,
        uint32_t b0, uint32_t b1) {
    asm volatile("mma.sync.aligned.m16n8k16.row.col.f32.bf16.bf16.f32 "
        "{%0,%1,%2,%3},{%4,%5,%6,%7},{%8,%9},{%0,%1,%2,%3};"
        : "+f"(c[0]), "+f"(c[1]), "+f"(c[2]), "+f"(c[3])
        : "r"(a0), "r"(a1), "r"(a2), "r"(a3), "r"(b0), "r"(b1));
}

__device__ __forceinline__ void split1(float v, __nv_bfloat16& h, __nv_bfloat16& l) {
    h = __float2bfloat16(v);
    l = __float2bfloat16(v - __bfloat162float(h));
}

union BP4 { unsigned long long u; __nv_bfloat16 h[4]; };

// ---------------- router + x-split fused (1st kernel) ------------------------
__global__ void router_k(const float* __restrict__ x,
                         const float* __restrict__ rw,
                         const float* __restrict__ rb) {
    int t = blockIdx.x;
    if (t == 0 && threadIdx.x < EE) g_count[threadIdx.x] = 0;

    {
        const float4* xr4 = (const float4*)(x + (size_t)t * DD);
        __nv_bfloat162* ph = (__nv_bfloat162*)(d_xh + (size_t)t * DD);
        __nv_bfloat162* pl = (__nv_bfloat162*)(d_xl + (size_t)t * DD);
#pragma unroll
        for (int i = 0; i < 2; i++) {
            int j = threadIdx.x + 128*i;
            float4 v = xr4[j];
            __nv_bfloat16 h0,l0,h1,l1,h2,l2,h3,l3;
            split1(v.x,h0,l0); split1(v.y,h1,l1);
            split1(v.z,h2,l2); split1(v.w,h3,l3);
            ph[j*2]   = __nv_bfloat162(h0,h1);  ph[j*2+1] = __nv_bfloat162(h2,h3);
            pl[j*2]   = __nv_bfloat162(l0,l1);  pl[j*2+1] = __nv_bfloat162(l2,l3);
        }
    }

    const float* xr = x + (size_t)t * DD;
    float acc[EE];
#pragma unroll
    for (int e = 0; e < EE; e++) acc[e] = 0.f;
    for (int d = threadIdx.x; d < DD; d += 128) {
        float xv = xr[d];
        const float4* r = (const float4*)(rw + (size_t)d * EE);
        float4 r0 = r[0], r1 = r[1];
        acc[0] += xv*r0.x; acc[1] += xv*r0.y; acc[2] += xv*r0.z; acc[3] += xv*r0.w;
        acc[4] += xv*r1.x; acc[5] += xv*r1.y; acc[6] += xv*r1.z; acc[7] += xv*r1.w;
    }
    __shared__ float sm[EE][128];
#pragma unroll
    for (int e = 0; e < EE; e++) sm[e][threadIdx.x] = acc[e];
    __syncthreads();
    for (int s = 64; s > 0; s >>= 1) {
        if (threadIdx.x < s)
#pragma unroll
            for (int e = 0; e < EE; e++) sm[e][threadIdx.x] += sm[e][threadIdx.x + s];
        __syncthreads();
    }
    if (threadIdx.x < EE)
        g_logits[(size_t)t*EE + threadIdx.x] = sm[threadIdx.x][0] + rb[threadIdx.x];
}

__global__ void norm_k() {
    int b = blockIdx.x >> 3, e = blockIdx.x & 7;
    float s = 0.f;
    for (int i = threadIdx.x; i < SS; i += 256) {
        float v = g_logits[((size_t)(b*SS + i))*EE + e];
        s += v*v;
    }
    __shared__ float sm[256];
    sm[threadIdx.x] = s; __syncthreads();
    for (int st = 128; st > 0; st >>= 1) {
        if (threadIdx.x < st) sm[threadIdx.x] += sm[threadIdx.x + st];
        __syncthreads();
    }
    if (threadIdx.x == 0) g_nrm[blockIdx.x] = fmaxf(sqrtf(sm[0]), 1e-12f);
}

__global__ void route_k() {
    int t = blockIdx.x*blockDim.x + threadIdx.x;
    if (t >= TT) return;
    int b = t / SS;
    float l[EE]; float m = -1e30f;
#pragma unroll
    for (int e = 0; e < EE; e++) {
        l[e] = g_logits[(size_t)t*EE + e] / g_nrm[b*EE + e];
        m = fmaxf(m, l[e]);
    }
    float sum = 0.f;
#pragma unroll
    for (int e = 0; e < EE; e++) { l[e] = expf(l[e]-m); sum += l[e]; }
    float inv = 1.f/sum;
#pragma unroll
    for (int e = 0; e < EE; e++) { l[e] *= inv; g_probs[(size_t)t*EE + e] = l[e]; }
    int i0 = 0;
#pragma unroll
    for (int e = 1; e < EE; e++) if (l[e] > l[i0]) i0 = e;
    int i1 = -1;
#pragma unroll
    for (int e = 0; e < EE; e++) {
        if (e == i0) continue;
        if (i1 < 0 || l[e] > l[i1]) i1 = e;
    }
    int s0 = atomicAdd(&g_count[i0], 1);
    g_tok[i0*TT + s0] = t; g_wt[i0*TT + s0] = l[i0];
    int s1 = atomicAdd(&g_count[i1], 1);
    g_tok[i1*TT + s1] = t; g_wt[i1*TT + s1] = l[i1];
}

__global__ void aux_k(float* __restrict__ out_aux) {
    float acc = 0.f;
    for (int i = threadIdx.x; i < SS*EE; i += 256) {
        int s = i >> 3, e = i & 7;
        float a = 0.5f*(g_probs[(size_t)s*EE + e] + g_probs[(size_t)(SS+s)*EE + e]);
        float d = 0.125f - a;
        acc += d*d;
    }
    __shared__ float sm[256];
    sm[threadIdx.x] = acc; __syncthreads();
    for (int st = 128; st > 0; st >>= 1) {
        if (threadIdx.x < st) sm[threadIdx.x] += sm[threadIdx.x + st];
        __syncthreads();
    }
    if (threadIdx.x == 0) out_aux[0] = sm[0];
}

// ---------------- GEMM1 (HMMA, 1-sync pipelined, 2 CTAs/SM) ------------------
#define G1_AB(p)  ((p)*16384)
#define G1_BB(p)  (32768 + (p)*16384)
#define G1_ST(q)  (65536 + (q)*16384)
#define G1_SMEM   98816
#define G1_NS     (DD/32)

__global__ __launch_bounds__(256, 2)
void gemm1_k(const float* __restrict__ w1, const float* __restrict__ w3) {
    extern __shared__ char smem[];
    int e = blockIdx.z;
    int cnt = g_count[e];
    int row0 = blockIdx.y * 128;
    if (row0 >= cnt) return;
    int col0 = blockIdx.x * 64;

    int tid = threadIdx.x, wid = tid >> 5, lane = tid & 31;
    uint32_t sb = smem_u32(smem);
    int* stok = (int*)(smem + 98304);

    if (tid < 128) stok[tid] = g_tok[e*TT + min(row0 + tid, cnt-1)];
    __syncthreads();

    int warpM = (wid & 1) * 64;
    int warpN = (wid >> 1) * 16;
    int fr  = (lane & 7) + ((lane >> 3) & 1) * 8;
    int fkb = (lane >> 4) * 16;

    auto cpA = [&](int s) {
        int kk = s*32;
        uint32_t base = sb + G1_AB(s & 1);
#pragma unroll
        for (int i = 0; i < 4; i++) {
            int g = tid + 256*i;
            int buf = g >> 9, idx = g & 511;
            int row = idx >> 2, c = idx & 3;
            const __nv_bfloat16* src =
                (buf ? d_xl : d_xh) + (size_t)stok[row]*DD + kk + c*8;
            cp16(base + buf*8192 + SW64(row*64 + c*16), src);
        }
    };
    auto cpB32 = [&](int s) {
        int kk = s*32;
        uint32_t base = sb + G1_ST(s & 1);
#pragma unroll
        for (int i = 0; i < 4; i++) {
            int g = tid + 256*i;
            int mat = g >> 9, idx = g & 511;
            int krow = idx >> 4, nch = idx & 15;
            const float* wp = mat ? w3 : w1;
            cp16(base + mat*8192 + krow*256 + nch*16,
                 wp + ((size_t)(e*DD + kk + krow))*HH + col0 + nch*4);
        }
    };
    auto convB = [&](int j) {
        char* src = smem + G1_ST(j & 1);
        char* dst = smem + G1_BB(j & 1);
#pragma unroll
        for (int i = 0; i < 4; i++) {
            int g = tid + 256*i;
            int mat = g >> 9, idx = g & 511;
            int krow = idx >> 4, nch = idx & 15;
            float4 v = *(float4*)(src + mat*8192 + krow*256 + nch*16);
            BP4 ph, pl;
            split1(v.x, ph.h[0], pl.h[0]);
            split1(v.y, ph.h[1], pl.h[1]);
            split1(v.z, ph.h[2], pl.h[2]);
            split1(v.w, ph.h[3], pl.h[3]);
            uint32_t off = SW128(krow*128 + nch*8);
            *(unsigned long long*)(dst + mat*8192 + off)        = ph.u;
            *(unsigned long long*)(dst + mat*8192 + 4096 + off) = pl.u;
        }
    };

    float c1[4][2][4], c3[4][2][4];
#pragma unroll
    for (int i = 0; i < 4; i++)
#pragma unroll
        for (int j = 0; j < 2; j++)
#pragma unroll
            for (int r = 0; r < 4; r++) { c1[i][j][r] = 0.f; c3[i][j][r] = 0.f; }

    cpA(0); cpB32(0); cpB32(1); CP_COMMIT();
    CP_WAIT0(); __syncthreads();
    convB(0);
    __syncthreads();

    for (int s = 0; s < G1_NS; s++) {
        int p = s & 1;
        if (s + 1 < G1_NS) cpA(s + 1);
        if (s + 2 < G1_NS) cpB32(s + 2);
        CP_COMMIT();
        if (s + 1 < G1_NS) convB(s + 1);   // overlaps with MMA below

        uint32_t ab = sb + G1_AB(p), bb = sb + G1_BB(p);
#pragma unroll
        for (int k16 = 0; k16 < 2; k16++) {
            // B fragments first (shared across all mt)
            uint32_t offB = SW128((k16*16 + fr)*128 + warpN*2 + fkb);
            uint32_t b1h[4], b1l[4], b3h[4], b3l[4];
            ldsm4t(b1h[0], b1h[1], b1h[2], b1h[3], bb + offB);
            ldsm4t(b1l[0], b1l[1], b1l[2], b1l[3], bb + 4096 + offB);
            ldsm4t(b3h[0], b3h[1], b3h[2], b3h[3], bb + 8192 + offB);
            ldsm4t(b3l[0], b3l[1], b3l[2], b3l[3], bb + 12288 + offB);
            // per-mt: A loads immediately followed by their 12 MMAs
#pragma unroll
            for (int mt = 0; mt < 4; mt++) {
                uint32_t offA = SW64((warpM + mt*16 + fr)*64 + k16*32 + fkb);
                uint32_t ah[4], al[4];
                ldsm4(ah[0], ah[1], ah[2], ah[3], ab + offA);
                ldsm4(al[0], al[1], al[2], al[3], ab + 8192 + offA);
#pragma unroll
                for (int nt = 0; nt < 2; nt++) {
                    mma16816(c1[mt][nt], ah[0],ah[1],ah[2],ah[3], b1h[nt*2], b1h[nt*2+1]);
                    mma16816(c3[mt][nt], ah[0],ah[1],ah[2],ah[3], b3h[nt*2], b3h[nt*2+1]);
                    mma16816(c1[mt][nt], al[0],al[1],al[2],al[3], b1h[nt*2], b1h[nt*2+1]);
                    mma16816(c3[mt][nt], al[0],al[1],al[2],al[3], b3h[nt*2], b3h[nt*2+1]);
                    mma16816(c1[mt][nt], ah[0],ah[1],ah[2],ah[3], b1l[nt*2], b1l[nt*2+1]);
                    mma16816(c3[mt][nt], ah[0],ah[1],ah[2],ah[3], b3l[nt*2], b3l[nt*2+1]);
                }
            }
        }

        if (s + 1 < G1_NS) { CP_WAIT0(); __syncthreads(); }
    }

    // epilogue
#pragma unroll
    for (int mt = 0; mt < 4; mt++) {
#pragma unroll
        for (int half = 0; half < 2; half++) {
            int rg = row0 + warpM + mt*16 + (lane >> 2) + half*8;
            if (rg < cnt) {
                size_t rowi = (size_t)(e*TT + rg);
                size_t cb = col0 + warpN + (lane & 3)*2;
#pragma unroll
                for (int nt = 0; nt < 2; nt++) {
                    float s0 = c1[mt][nt][half*2],   g0 = c3[mt][nt][half*2];
                    float s1 = c1[mt][nt][half*2+1], g1 = c3[mt][nt][half*2+1];
                    float v0 = __sinf(s0)*g0, v1 = __sinf(s1)*g1;
                    __nv_bfloat16 h0,l0,h1,l1;
                    split1(v0,h0,l0); split1(v1,h1,l1);
                    *(__nv_bfloat162*)(d_h2 + (rowi*2)*HH   + cb + nt*8) = __nv_bfloat162(h0,h1);
                    *(__nv_bfloat162*)(d_h2 + (rowi*2+1)*HH + cb + nt*8) = __nv_bfloat162(l0,l1);
                }
            }
        }
    }
}

// ---------------- GEMM2 (HMMA, 1-sync pipelined, 2 CTAs/SM) ------------------
#define G2_AB(p)  ((p)*16384)
#define G2_BB(p)  (32768 + (p)*8192)
#define G2_ST(q)  (49152 + (q)*8192)
#define G2_SMEM   66560
#define G2_NS     (HH/32)

__global__ __launch_bounds__(256, 2)
void gemm2_k(const float* __restrict__ w2, float* __restrict__ out) {
    extern __shared__ char smem[];
    int e = blockIdx.z;
    int cnt = g_count[e];
    int row0 = blockIdx.y * 128;
    if (row0 >= cnt) return;
    int col0 = blockIdx.x * 64;

    int tid = threadIdx.x, wid = tid >> 5, lane = tid & 31;
    uint32_t sb = smem_u32(smem);
    int*   stok = (int*)(smem + 65536);
    float* swt  = (float*)(smem + 65536 + 512);

    if (tid < 128) {
        int r = min(row0 + tid, cnt-1);
        stok[tid] = g_tok[e*TT + r];
        swt[tid]  = g_wt[e*TT + r];
    }
    __syncthreads();

    int warpM = (wid & 1) * 64;
    int warpN = (wid >> 1) * 16;
    int fr  = (lane & 7) + ((lane >> 3) & 1) * 8;
    int fkb = (lane >> 4) * 16;
    size_t arow0 = (size_t)(e*TT + row0);

    auto cpA = [&](int s) {
        int kk = s*32;
        uint32_t base = sb + G2_AB(s & 1);
#pragma unroll
        for (int i = 0; i < 4; i++) {
            int g = tid + 256*i;
            int buf = g >> 9, idx = g & 511;
            int row = idx >> 2, c = idx & 3;
            const __nv_bfloat16* src =
                d_h2 + ((arow0 + row)*2 + buf)*HH + kk + c*8;
            cp16(base + buf*8192 + SW64(row*64 + c*16), src);
        }
    };
    auto cpB32 = [&](int s) {
        int kk = s*32;
        uint32_t base = sb + G2_ST(s & 1);
#pragma unroll
        for (int i = 0; i < 2; i++) {
            int g = tid + 256*i;
            int krow = g >> 4, nch = g & 15;
            cp16(base + krow*256 + nch*16,
                 w2 + ((size_t)(e*HH + kk + krow))*DD + col0 + nch*4);
        }
    };
    auto convB = [&](int j) {
        char* src = smem + G2_ST(j & 1);
        char* dst = smem + G2_BB(j & 1);
#pragma unroll
        for (int i = 0; i < 2; i++) {
            int g = tid + 256*i;
            int krow = g >> 4, nch = g & 15;
            float4 v = *(float4*)(src + krow*256 + nch*16);
            BP4 ph, pl;
            split1(v.x, ph.h[0], pl.h[0]);
            split1(v.y, ph.h[1], pl.h[1]);
            split1(v.z, ph.h[2], pl.h[2]);
            split1(v.w, ph.h[3], pl.h[3]);
            uint32_t off = SW128(krow*128 + nch*8);
            *(unsigned long long*)(dst + off)        = ph.u;
            *(unsigned long long*)(dst + 4096 + off) = pl.u;
        }
    };

    float cc[4][2][4];
#pragma unroll
    for (int i = 0; i < 4; i++)
#pragma unroll
        for (int j = 0; j < 2; j++)
#pragma unroll
            for (int r = 0; r < 4; r++) cc[i][j][r] = 0.f;

    cpA(0); cpB32(0); cpB32(1); CP_COMMIT();
    CP_WAIT0(); __syncthreads();
    convB(0);
    __syncthreads();

    for (int s = 0; s < G2_NS; s++) {
        int p = s & 1;
        if (s + 1 < G2_NS) cpA(s + 1);
        if (s + 2 < G2_NS) cpB32(s + 2);
        CP_COMMIT();
        if (s + 1 < G2_NS) convB(s + 1);

        uint32_t ab = sb + G2_AB(p), bb = sb + G2_BB(p);
#pragma unroll
        for (int k16 = 0; k16 < 2; k16++) {
            uint32_t offB = SW128((k16*16 + fr)*128 + warpN*2 + fkb);
            uint32_t bh[4], bl[4];
            ldsm4t(bh[0], bh[1], bh[2], bh[3], bb + offB);
            ldsm4t(bl[0], bl[1], bl[2], bl[3], bb + 4096 + offB);
#pragma unroll
            for (int mt = 0; mt < 4; mt++) {
                uint32_t offA = SW64((warpM + mt*16 + fr)*64 + k16*32 + fkb);
                uint32_t ah[4], al[4];
                ldsm4(ah[0], ah[1], ah[2], ah[3], ab + offA);
                ldsm4(al[0], al[1], al[2], al[3], ab + 8192 + offA);
#pragma unroll
                for (int nt = 0; nt < 2; nt++) {
                    mma16816(cc[mt][nt], ah[0],ah[1],ah[2],ah[3], bh[nt*2], bh[nt*2+1]);
                    mma16816(cc[mt][nt], al[0],al[1],al[2],al[3], bh[nt*2], bh[nt*2+1]);
                    mma16816(cc[mt][nt], ah[0],ah[1],ah[2],ah[3], bl[nt*2], bl[nt*2+1]);
                }
            }
        }

        if (s + 1 < G2_NS) { CP_WAIT0(); __syncthreads(); }
    }

    // epilogue: weighted atomic scatter
#pragma unroll
    for (int mt = 0; mt < 4; mt++) {
#pragma unroll
        for (int half = 0; half < 2; half++) {
            int ml = warpM + mt*16 + (lane >> 2) + half*8;
            if (row0 + ml < cnt) {
                int   tok = stok[ml];
                float wt  = swt[ml];
                float* op = out + (size_t)tok*DD + col0 + warpN + (lane & 3)*2;
#pragma unroll
                for (int nt = 0; nt < 2; nt++) {
                    atomicAdd(op + nt*8 + 0, wt * cc[mt][nt][half*2]);
                    atomicAdd(op + nt*8 + 1, wt * cc[mt][nt][half*2+1]);
                }
            }
        }
    }
}

// ---------------- launch -----------------------------------------------------
extern "C" void kernel_launch(void* const* d_in, const int* in_sizes, int n_in,
                              void* d_out, int out_size) {
    const float* x  = (const float*)d_in[0];
    const float* w1 = (const float*)d_in[1];
    const float* w2 = (const float*)d_in[2];
    const float* w3 = (const float*)d_in[3];
    const float* rw = (const float*)d_in[4];
    const float* rb = (const float*)d_in[5];
    float* out = (float*)d_out;

    cudaFuncSetAttribute(gemm1_k, cudaFuncAttributeMaxDynamicSharedMemorySize, G1_SMEM);
    cudaFuncSetAttribute(gemm2_k, cudaFuncAttributeMaxDynamicSharedMemorySize, G2_SMEM);

    cudaMemsetAsync(d_out, 0, (size_t)out_size * sizeof(float));

    router_k<<<TT, 128>>>(x, rw, rb);                       // kernel 1 (+split+init)
    norm_k<<<BB*EE, 256>>>();                               // kernel 2
    route_k<<<TT/256, 256>>>();                             // kernel 3
    gemm1_k<<<dim3(HH/64, TT/128, EE), 256, G1_SMEM>>>(w1, w3);   // kernel 4 (ncu)
    gemm2_k<<<dim3(DD/64, TT/128, EE), 256, G2_SMEM>>>(w2, out);  // kernel 5
    if (out_size > TT*DD) aux_k<<<1, 256>>>(out + (size_t)TT*DD); // kernel 6
}